// round 15
// baseline (speedup 1.0000x reference)
#include <cuda_runtime.h>
#include <cuda_bf16.h>
#include <cstddef>

// ---------------------------------------------------------------------------
// Problem constants
// ---------------------------------------------------------------------------
#define BATCH 32
#define SEQT  512
#define DMOD  512
#define HID   256
#define G4    1024          // 4*HID
#define ENT   64
#define REL   64
#define NLAY  2
#define MBT   (BATCH*SEQT)          // 16384 token rows
#define MPAIR (BATCH*ENT*ENT)       // 131072 pair rows
#define MENT  (BATCH*ENT)           // 2048 entity rows

// ---------------------------------------------------------------------------
// Device scratch (static allocation only — no cudaMalloc allowed)
// ---------------------------------------------------------------------------
__device__ __nv_bfloat16  g_xb[(size_t)MBT * DMOD];        // bf16 activations
__device__ float          g_xw[(size_t)2 * MBT * G4];      // per-dir input proj (fp32)
__device__ float          g_bias[NLAY * 2 * G4];           // bih+bhh
__device__ int            g_sents[MBT];
__device__ int            g_ent[MENT * 3];
__device__ float          g_cont[(size_t)MENT * DMOD];
__device__ float          g_mask[MENT];
__device__ float          g_cw[(size_t)MENT * DMOD];
__device__ __nv_bfloat16  g_cwb[(size_t)MENT * DMOD];
__device__ float          g_rel1[(size_t)MENT * DMOD];
__device__ float          g_rel2[(size_t)MENT * DMOD];
__device__ __nv_bfloat16  g_Tb[(size_t)MPAIR * DMOD];      // pair hidden, bf16
// bf16 weight copies
__device__ __nv_bfloat16  g_wihb[(size_t)NLAY * 2 * G4 * DMOD];
__device__ __nv_bfloat16  g_r1b[DMOD * DMOD];
__device__ __nv_bfloat16  g_r2b[DMOD * DMOD];
__device__ __nv_bfloat16  g_pjb[DMOD * DMOD];
__device__ __nv_bfloat16  g_dcb[REL * DMOD];

__device__ __forceinline__ float tanh_a(float x) {
    float r;
    asm("tanh.approx.f32 %0, %1;" : "=f"(r) : "f"(x));
    return r;
}
__device__ __forceinline__ float sigm_a(float x) {
    return fmaf(tanh_a(0.5f * x), 0.5f, 0.5f);
}

// ---------------------------------------------------------------------------
// K0: canonicalize sents / ent_inds (int64-or-int32 auto-detect) -> int32
// ---------------------------------------------------------------------------
__global__ void prep_idx_kernel(const unsigned* __restrict__ sents_raw,
                                const unsigned* __restrict__ ent_raw) {
    __shared__ int s64f, e64f;
    int tid = threadIdx.x;
    if (tid == 0) {
        bool s64 = true;
        for (int i = 0; i < 64; i++)
            if (sents_raw[2 * i + 1] != 0u) { s64 = false; break; }
        bool e64 = true;
        for (int i = 0; i < 64; i++) {
            unsigned lo = ent_raw[2 * i], hi = ent_raw[2 * i + 1];
            unsigned expct = ((int)lo < 0) ? 0xFFFFFFFFu : 0u;
            if (hi != expct) { e64 = false; break; }
        }
        s64f = s64; e64f = e64;
    }
    __syncthreads();
    int s64 = s64f, e64 = e64f;
    for (int i = tid; i < MBT; i += blockDim.x)
        g_sents[i] = s64 ? (int)sents_raw[2 * i] : (int)sents_raw[i];
    for (int i = tid; i < MENT * 3; i += blockDim.x)
        g_ent[i] = e64 ? (int)ent_raw[2 * i] : (int)ent_raw[i];
}

__global__ void prep_bias_kernel(const float* __restrict__ bih,
                                 const float* __restrict__ bhh) {
    int i = blockIdx.x * blockDim.x + threadIdx.x;
    if (i < NLAY * 2 * G4) g_bias[i] = bih[i] + bhh[i];
}

// ---------------------------------------------------------------------------
// f32 -> bf16 vectorized convert (n4 float4-groups)
// ---------------------------------------------------------------------------
__global__ void f2b_kernel(const float* __restrict__ src,
                           __nv_bfloat16* __restrict__ dst, int n4) {
    int i = blockIdx.x * blockDim.x + threadIdx.x;
    if (i >= n4) return;
    float4 v = reinterpret_cast<const float4*>(src)[i];
    __nv_bfloat162 lo = __float22bfloat162_rn(make_float2(v.x, v.y));
    __nv_bfloat162 hi = __float22bfloat162_rn(make_float2(v.z, v.w));
    uint2 u;
    u.x = *reinterpret_cast<unsigned*>(&lo);
    u.y = *reinterpret_cast<unsigned*>(&hi);
    reinterpret_cast<uint2*>(dst)[i] = u;
}

// ---------------------------------------------------------------------------
// K2: embedding gather -> bf16 activations
// ---------------------------------------------------------------------------
__global__ void embed_kernel(const float* __restrict__ emb) {
    int row = blockIdx.x;
    int d = threadIdx.x;                               // 128 float4 lanes
    int tok = g_sents[row];
    float4 v = reinterpret_cast<const float4*>(emb + (size_t)tok * DMOD)[d];
    __nv_bfloat162 lo = __float22bfloat162_rn(make_float2(v.x, v.y));
    __nv_bfloat162 hi = __float22bfloat162_rn(make_float2(v.z, v.w));
    uint2 u;
    u.x = *reinterpret_cast<unsigned*>(&lo);
    u.y = *reinterpret_cast<unsigned*>(&hi);
    reinterpret_cast<uint2*>(g_xb + (size_t)row * DMOD)[d] = u;
}

// ---------------------------------------------------------------------------
// bf16 tensor-core GEMM: C[M,N] = A[M,K] @ W[N,K]^T + bias, fp32 accum.
// BM=128 BN=64 BK=32, 256 thr (8 warps, 4x2), warp tile 32x32 via mma.m16n8k16.
// Double-buffered smem (1 syncthreads per k-tile) + ldmatrix.x4 fragment loads.
// GEN: A generated on the fly as relu(r1[b,j]+r2[b,i]); OUTB: bf16 output.
// ---------------------------------------------------------------------------
template <bool GEN, bool OUTB, bool RELU>
__global__ __launch_bounds__(256)
void hgemm_nt(const __nv_bfloat16* __restrict__ A,
              const __nv_bfloat16* __restrict__ Bw,
              const float* __restrict__ bias,
              float* __restrict__ Cf, __nv_bfloat16* __restrict__ Cb,
              int M, int N, int K,
              const float* __restrict__ r1, const float* __restrict__ r2) {
    const int BM = 128, BN = 64, BK = 32, LDA = BK + 8;   // 80-byte rows (16B mult)
    __shared__ __align__(16) __nv_bfloat16 As[2][BM * LDA];
    __shared__ __align__(16) __nv_bfloat16 Bs[2][BN * LDA];
    int tid = threadIdx.x;
    int row0 = blockIdx.y * BM, col0 = blockIdx.x * BN;

    int ar[2], ac[2];
    #pragma unroll
    for (int q = 0; q < 2; q++) {
        int idx = tid + q * 256;
        ar[q] = idx >> 2;
        ac[q] = (idx & 3) * 8;
    }
    int br = tid >> 2, bc = (tid & 3) * 8;

    float acc[2][4][4];
    #pragma unroll
    for (int i = 0; i < 2; i++)
        #pragma unroll
        for (int j = 0; j < 4; j++)
            #pragma unroll
            for (int c = 0; c < 4; c++) acc[i][j][c] = 0.f;

    uint4 ua[2], ub;
    auto fetch = [&](int kt) {
        #pragma unroll
        for (int q = 0; q < 2; q++) {
            int m = row0 + ar[q];
            if (!GEN) {
                ua[q] = *reinterpret_cast<const uint4*>(A + (size_t)m * K + kt + ac[q]);
            } else {
                int bb = m >> 12, ii = (m >> 6) & 63, jj = m & 63;
                const float4* p1 = reinterpret_cast<const float4*>(
                    r1 + ((size_t)(bb * ENT + jj)) * DMOD + kt + ac[q]);
                const float4* p2 = reinterpret_cast<const float4*>(
                    r2 + ((size_t)(bb * ENT + ii)) * DMOD + kt + ac[q]);
                float4 x0 = p1[0], x1 = p1[1], y0 = p2[0], y1 = p2[1];
                float f0 = fmaxf(x0.x + y0.x, 0.f), f1 = fmaxf(x0.y + y0.y, 0.f);
                float f2 = fmaxf(x0.z + y0.z, 0.f), f3 = fmaxf(x0.w + y0.w, 0.f);
                float f4 = fmaxf(x1.x + y1.x, 0.f), f5 = fmaxf(x1.y + y1.y, 0.f);
                float f6 = fmaxf(x1.z + y1.z, 0.f), f7 = fmaxf(x1.w + y1.w, 0.f);
                __nv_bfloat162 h0 = __float22bfloat162_rn(make_float2(f0, f1));
                __nv_bfloat162 h1 = __float22bfloat162_rn(make_float2(f2, f3));
                __nv_bfloat162 h2 = __float22bfloat162_rn(make_float2(f4, f5));
                __nv_bfloat162 h3 = __float22bfloat162_rn(make_float2(f6, f7));
                ua[q].x = *reinterpret_cast<unsigned*>(&h0);
                ua[q].y = *reinterpret_cast<unsigned*>(&h1);
                ua[q].z = *reinterpret_cast<unsigned*>(&h2);
                ua[q].w = *reinterpret_cast<unsigned*>(&h3);
            }
        }
        ub = *reinterpret_cast<const uint4*>(Bw + (size_t)(col0 + br) * K + kt + bc);
    };
    auto stage = [&](int buf) {
        *reinterpret_cast<uint4*>(&As[buf][ar[0] * LDA + ac[0]]) = ua[0];
        *reinterpret_cast<uint4*>(&As[buf][ar[1] * LDA + ac[1]]) = ua[1];
        *reinterpret_cast<uint4*>(&Bs[buf][br * LDA + bc]) = ub;
    };

    int w = tid >> 5, wm = w & 3, wn = w >> 2, l = tid & 31;
    int lr = l >> 2, lc = (l & 3) * 2;

    int a_row = wm * 32 + ((l >> 3) & 1) * 8 + (l & 7);
    int a_col = (l >> 4) * 8;
    int b_row = wn * 32 + (l >> 4) * 8 + (l & 7);
    int b_col = ((l >> 3) & 1) * 8;
    unsigned sAu = (unsigned)__cvta_generic_to_shared(&As[0][0]);
    unsigned sBu = (unsigned)__cvta_generic_to_shared(&Bs[0][0]);
    const unsigned bufAB = (unsigned)(BM * LDA * 2);
    const unsigned bufBB = (unsigned)(BN * LDA * 2);
    unsigned aAddr = sAu + (unsigned)((a_row * LDA + a_col) * 2);
    unsigned bAddr = sBu + (unsigned)((b_row * LDA + b_col) * 2);

    fetch(0);
    stage(0);
    __syncthreads();

    int nk = K / BK;
    for (int kt = 0; kt < nk; kt++) {
        int cur = kt & 1;
        if (kt + 1 < nk) fetch((kt + 1) * BK);

        unsigned aBuf = aAddr + cur * bufAB;
        unsigned bBuf = bAddr + cur * bufBB;
        #pragma unroll
        for (int s = 0; s < 2; s++) {
            unsigned a[2][4], b[4][2];
            #pragma unroll
            for (int i = 0; i < 2; i++) {
                unsigned ad = aBuf + (unsigned)((i * 16 * LDA + s * 16) * 2);
                asm volatile(
                    "ldmatrix.sync.aligned.m8n8.x4.shared.b16 {%0,%1,%2,%3}, [%4];"
                    : "=r"(a[i][0]), "=r"(a[i][1]), "=r"(a[i][2]), "=r"(a[i][3])
                    : "r"(ad));
            }
            #pragma unroll
            for (int jp = 0; jp < 2; jp++) {
                unsigned bd = bBuf + (unsigned)((jp * 16 * LDA + s * 16) * 2);
                asm volatile(
                    "ldmatrix.sync.aligned.m8n8.x4.shared.b16 {%0,%1,%2,%3}, [%4];"
                    : "=r"(b[2 * jp][0]), "=r"(b[2 * jp][1]),
                      "=r"(b[2 * jp + 1][0]), "=r"(b[2 * jp + 1][1])
                    : "r"(bd));
            }
            #pragma unroll
            for (int i = 0; i < 2; i++)
                #pragma unroll
                for (int j = 0; j < 4; j++)
                    asm volatile(
                        "mma.sync.aligned.m16n8k16.row.col.f32.bf16.bf16.f32 "
                        "{%0,%1,%2,%3},{%4,%5,%6,%7},{%8,%9},{%0,%1,%2,%3};"
                        : "+f"(acc[i][j][0]), "+f"(acc[i][j][1]),
                          "+f"(acc[i][j][2]), "+f"(acc[i][j][3])
                        : "r"(a[i][0]), "r"(a[i][1]), "r"(a[i][2]), "r"(a[i][3]),
                          "r"(b[j][0]), "r"(b[j][1]));
        }

        if (kt + 1 < nk) {
            stage(cur ^ 1);
            __syncthreads();
        }
    }

    // epilogue
    #pragma unroll
    for (int i = 0; i < 2; i++) {
        int m = row0 + wm * 32 + i * 16 + lr;
        #pragma unroll
        for (int j = 0; j < 4; j++) {
            int col = col0 + wn * 32 + j * 8 + lc;
            float b0 = bias[col], b1 = bias[col + 1];
            float v0 = acc[i][j][0] + b0, v1 = acc[i][j][1] + b1;
            float v2 = acc[i][j][2] + b0, v3 = acc[i][j][3] + b1;
            if (RELU) {
                v0 = fmaxf(v0, 0.f); v1 = fmaxf(v1, 0.f);
                v2 = fmaxf(v2, 0.f); v3 = fmaxf(v3, 0.f);
            }
            if (OUTB) {
                __nv_bfloat162 p0 = __float22bfloat162_rn(make_float2(v0, v1));
                __nv_bfloat162 p1 = __float22bfloat162_rn(make_float2(v2, v3));
                *reinterpret_cast<__nv_bfloat162*>(Cb + (size_t)m * N + col) = p0;
                *reinterpret_cast<__nv_bfloat162*>(Cb + (size_t)(m + 8) * N + col) = p1;
            } else {
                *reinterpret_cast<float2*>(Cf + (size_t)m * N + col) = make_float2(v0, v1);
                *reinterpret_cast<float2*>(Cf + (size_t)(m + 8) * N + col) = make_float2(v2, v3);
            }
        }
    }
}

// ---------------------------------------------------------------------------
// K3: LSTM recurrence on tensor cores, 4-CTA cluster, TWO interleaved chains.
// Cluster = (dir, 4 batches): chain A = batches bg0,bg0+1; chain B = bg0+2,+3.
// Both chains share the register-resident Whh slice (same dir). Per iteration
// both chains advance one step with ONE __syncthreads and ONE cluster.sync:
// mma(A); mma(B); sync; all 256 threads are owners (128/chain), broadcast h
// via DSMEM for both chains; arrive; y stores; wait. Barrier cost per chain-
// step halves and B's mma issue hides A's exchange latency.
// ---------------------------------------------------------------------------
__global__ void __cluster_dims__(4, 1, 1) __launch_bounds__(256, 1)
lstm_mma_kernel(const float* __restrict__ xw,
                const float* __restrict__ whh_l,   // fp32 [2][G4][HID]
                __nv_bfloat16* __restrict__ yb) {
    __shared__ __align__(16) __nv_bfloat16 hA[2][2][2][264]; // [chain][par][batch][k]
    __shared__ __align__(16) float zs[2][2][260];            // [chain][batch][n]

    int tid = threadIdx.x;
    int w = tid >> 5, l = tid & 31;
    int gq = l >> 2, t2 = (l & 3) * 2;
    int rank = blockIdx.x & 3;
    int cid  = blockIdx.x >> 2;          // 0..15
    int dir  = cid >> 3;
    int grp  = cid & 7;
    int bg0  = grp * 4;
    int j0   = rank * 64;

    // zero h staging (all chains/parities)
    for (int i = tid; i < 2 * 2 * 2 * 264; i += 256)
        (&hA[0][0][0][0])[i] = __float2bfloat16(0.f);

    // ---- B-fragment preload: W[n][k] resident in registers ----------------
    unsigned Bf[4][16][2];
    {
        const float* wd = whh_l + (size_t)dir * G4 * HID;
        #pragma unroll
        for (int nt = 0; nt < 4; nt++) {
            int n = w * 32 + nt * 8 + gq;            // CTA-local gate index
            int g = n >> 6, jl = n & 63;
            const float* wp = wd + (size_t)(g * 256 + j0 + jl) * HID;
            #pragma unroll
            for (int kt = 0; kt < 16; kt++) {
                int k0 = kt * 16 + t2;
                float2 wa = *reinterpret_cast<const float2*>(wp + k0);
                float2 wb = *reinterpret_cast<const float2*>(wp + k0 + 8);
                __nv_bfloat162 qa = __float22bfloat162_rn(wa);
                __nv_bfloat162 qb = __float22bfloat162_rn(wb);
                Bf[nt][kt][0] = *reinterpret_cast<unsigned*>(&qa);
                Bf[nt][kt][1] = *reinterpret_cast<unsigned*>(&qb);
            }
        }
    }
    __syncthreads();
    asm volatile("barrier.cluster.arrive.aligned;" ::: "memory");
    asm volatile("barrier.cluster.wait.aligned;" ::: "memory");

    const float* xd = xw + (size_t)dir * MBT * G4;
    int xcol = (w >> 1) * 256 + j0 + (w & 1) * 32;   // global z-col base
    int brow = gq & 1;                               // A-row (= batch-in-chain) lanes 0-7

    // per-chain x row bases (lanes 0-7 load)
    const float* xrowA = xd + (size_t)(bg0 + brow) * SEQT * G4;
    const float* xrowB = xd + (size_t)(bg0 + 2 + brow) * SEQT * G4;

    // owner mapping: all 256 threads. chain ch, batch-in-chain ob, j-local ojl
    int ch = tid >> 7, ob = (tid >> 6) & 1, ojl = tid & 63;
    int ojg = j0 + ojl;
    size_t yoff = ((size_t)(bg0 + ch * 2 + ob) * SEQT) * DMOD + dir * HID + ojg;
    float cst = 0.f;

    unsigned hAbase;
    asm("{ .reg .u64 t; cvta.to.shared.u64 t, %1; cvt.u32.u64 %0, t; }"
        : "=r"(hAbase) : "l"(&hA[0][0][0][0]));

    // first step's x (lanes 0-7), both chains
    float2 xiA[4], xiB[4];
    {
        int t0 = dir ? SEQT - 1 : 0;
        #pragma unroll
        for (int nt = 0; nt < 4; nt++) {
            xiA[nt] = make_float2(0.f, 0.f);
            xiB[nt] = make_float2(0.f, 0.f);
            if (l < 8) {
                xiA[nt] = *reinterpret_cast<const float2*>(
                    xrowA + (size_t)t0 * G4 + xcol + nt * 8 + t2);
                xiB[nt] = *reinterpret_cast<const float2*>(
                    xrowB + (size_t)t0 * G4 + xcol + nt * 8 + t2);
            }
        }
    }

    unsigned zc = 0u;
    int par = 0;
    for (int s = 0; s < SEQT; s++) {
        int t = dir ? (SEQT - 1 - s) : s;
        int sn = (s + 1 < SEQT) ? s + 1 : s;
        int tn = dir ? (SEQT - 1 - sn) : sn;

        // prefetch next step's x for both chains
        float2 xnA[4], xnB[4];
        #pragma unroll
        for (int nt = 0; nt < 4; nt++) {
            xnA[nt] = make_float2(0.f, 0.f);
            xnB[nt] = make_float2(0.f, 0.f);
            if (l < 8) {
                xnA[nt] = *reinterpret_cast<const float2*>(
                    xrowA + (size_t)tn * G4 + xcol + nt * 8 + t2);
                xnB[nt] = *reinterpret_cast<const float2*>(
                    xrowB + (size_t)tn * G4 + xcol + nt * 8 + t2);
            }
        }

        // ---- chain A: mma + z store ----
        {
            float acc[4][4];
            #pragma unroll
            for (int nt = 0; nt < 4; nt++) {
                acc[nt][0] = xiA[nt].x; acc[nt][1] = xiA[nt].y;
                acc[nt][2] = 0.f;       acc[nt][3] = 0.f;
            }
            const __nv_bfloat16* hrow = &hA[0][par][brow][0];
            #pragma unroll
            for (int kt = 0; kt < 16; kt++) {
                unsigned a0 = 0u, a2 = 0u;
                if (l < 8) {
                    a0 = *reinterpret_cast<const unsigned*>(hrow + kt * 16 + t2);
                    a2 = *reinterpret_cast<const unsigned*>(hrow + kt * 16 + t2 + 8);
                }
                #pragma unroll
                for (int nt = 0; nt < 4; nt++)
                    asm volatile(
                        "mma.sync.aligned.m16n8k16.row.col.f32.bf16.bf16.f32 "
                        "{%0,%1,%2,%3},{%4,%5,%6,%7},{%8,%9},{%0,%1,%2,%3};"
                        : "+f"(acc[nt][0]), "+f"(acc[nt][1]),
                          "+f"(acc[nt][2]), "+f"(acc[nt][3])
                        : "r"(a0), "r"(zc), "r"(a2), "r"(zc),
                          "r"(Bf[nt][kt][0]), "r"(Bf[nt][kt][1]));
            }
            if (l < 8) {
                #pragma unroll
                for (int nt = 0; nt < 4; nt++)
                    *reinterpret_cast<float2*>(&zs[0][brow][w * 32 + nt * 8 + t2]) =
                        make_float2(acc[nt][0], acc[nt][1]);
            }
        }

        // ---- chain B: mma + z store ----
        {
            float acc[4][4];
            #pragma unroll
            for (int nt = 0; nt < 4; nt++) {
                acc[nt][0] = xiB[nt].x; acc[nt][1] = xiB[nt].y;
                acc[nt][2] = 0.f;       acc[nt][3] = 0.f;
            }
            const __nv_bfloat16* hrow = &hA[1][par][brow][0];
            #pragma unroll
            for (int kt = 0; kt < 16; kt++) {
                unsigned a0 = 0u, a2 = 0u;
                if (l < 8) {
                    a0 = *reinterpret_cast<const unsigned*>(hrow + kt * 16 + t2);
                    a2 = *reinterpret_cast<const unsigned*>(hrow + kt * 16 + t2 + 8);
                }
                #pragma unroll
                for (int nt = 0; nt < 4; nt++)
                    asm volatile(
                        "mma.sync.aligned.m16n8k16.row.col.f32.bf16.bf16.f32 "
                        "{%0,%1,%2,%3},{%4,%5,%6,%7},{%8,%9},{%0,%1,%2,%3};"
                        : "+f"(acc[nt][0]), "+f"(acc[nt][1]),
                          "+f"(acc[nt][2]), "+f"(acc[nt][3])
                        : "r"(a0), "r"(zc), "r"(a2), "r"(zc),
                          "r"(Bf[nt][kt][0]), "r"(Bf[nt][kt][1]));
            }
            if (l < 8) {
                #pragma unroll
                for (int nt = 0; nt < 4; nt++)
                    *reinterpret_cast<float2*>(&zs[1][brow][w * 32 + nt * 8 + t2]) =
                        make_float2(acc[nt][0], acc[nt][1]);
            }
        }
        __syncthreads();

        // ---- owners: ALL 256 threads, one (chain, batch, j) each ----------
        float z0 = zs[ch][ob][0 * 64 + ojl];
        float z1 = zs[ch][ob][1 * 64 + ojl];
        float z2 = zs[ch][ob][2 * 64 + ojl];
        float z3 = zs[ch][ob][3 * 64 + ojl];
        cst = sigm_a(z1) * cst + sigm_a(z0) * tanh_a(z2);
        float h = sigm_a(z3) * tanh_a(cst);
        __nv_bfloat16 hbq = __float2bfloat16(h);

        unsigned uv = (unsigned)__bfloat16_as_ushort(hbq);
        unsigned nv = __shfl_down_sync(0xffffffffu, uv, 1);
        if (!(ojl & 1)) {
            unsigned pk = uv | (nv << 16);
            unsigned dst = hAbase +
                (unsigned)((((ch * 2 + (par ^ 1)) * 2 + ob) * 264 + ojg) * 2);
            #pragma unroll
            for (int r = 0; r < 4; r++) {
                asm volatile(
                    "{ .reg .b32 ra; mapa.shared::cluster.u32 ra, %0, %1; "
                    "st.shared::cluster.b32 [ra], %2; }"
                    :: "r"(dst), "r"(r), "r"(pk) : "memory");
            }
        }
        // arrive first; y store retires inside the barrier window
        asm volatile("barrier.cluster.arrive.aligned;" ::: "memory");
        yb[yoff + (size_t)t * DMOD] = hbq;
        asm volatile("barrier.cluster.wait.aligned;" ::: "memory");

        par ^= 1;
        #pragma unroll
        for (int nt = 0; nt < 4; nt++) { xiA[nt] = xnA[nt]; xiB[nt] = xnB[nt]; }
    }
}

// ---------------------------------------------------------------------------
// K4: zero cont + mask
// ---------------------------------------------------------------------------
__global__ void zero_kernel() {
    int idx = blockIdx.x * blockDim.x + threadIdx.x;
    const int NC4 = (MENT * DMOD) / 4;
    if (idx < NC4) reinterpret_cast<float4*>(g_cont)[idx] = make_float4(0, 0, 0, 0);
    if (idx < MENT / 4) reinterpret_cast<float4*>(g_mask)[idx] = make_float4(0, 0, 0, 0);
}

// ---------------------------------------------------------------------------
// K5: ragged span mean-pool + scatter-add (atomic); reads bf16 activations
// ---------------------------------------------------------------------------
__global__ void span_pool_kernel(const __nv_bfloat16* __restrict__ x) {
    int be = blockIdx.x;
    int b = be >> 6;
    const int* ei = g_ent + be * 3;
    int id = ei[0], st = ei[1], en = ei[2];
    if (id < 0 || id >= ENT) return;
    int lo = st, hi = en;
    float sgn = 1.f;
    if (en < st) { lo = en; hi = st; sgn = -1.f; }
    lo = max(lo, 0); hi = min(hi, SEQT);
    float len = (float)max(en - st, 1);

    int d = threadIdx.x;                 // 128 lanes, 4 bf16 each
    float4 acc = make_float4(0, 0, 0, 0);
    const uint2* xp =
        reinterpret_cast<const uint2*>(x + (size_t)b * SEQT * DMOD) + d;
    for (int t = lo; t < hi; t++) {
        uint2 u = xp[(size_t)t * (DMOD / 4)];
        float2 a = __bfloat1622float2(*reinterpret_cast<__nv_bfloat162*>(&u.x));
        float2 bb = __bfloat1622float2(*reinterpret_cast<__nv_bfloat162*>(&u.y));
        acc.x += a.x; acc.y += a.y; acc.z += bb.x; acc.w += bb.y;
    }
    float invl = sgn / len;
    float* cp = g_cont + ((size_t)(b * ENT + id)) * DMOD + d * 4;
    atomicAdd(cp + 0, acc.x * invl);
    atomicAdd(cp + 1, acc.y * invl);
    atomicAdd(cp + 2, acc.z * invl);
    atomicAdd(cp + 3, acc.w * invl);
    if (d == 0) atomicAdd(&g_mask[b * ENT + id], 1.f);
}

// ---------------------------------------------------------------------------
// K6: LayerNorm over D=512 -> fp32 cw
// ---------------------------------------------------------------------------
__global__ __launch_bounds__(256)
void ln_kernel(const float* __restrict__ gw, const float* __restrict__ gb) {
    int row = blockIdx.x;
    int tid = threadIdx.x;
    const float* xr = g_cont + (size_t)row * DMOD;
    float v0 = xr[tid], v1 = xr[tid + 256];

    __shared__ float red[8];
    __shared__ float bc;
    int lane = tid & 31, warp = tid >> 5;

    float s = v0 + v1;
    #pragma unroll
    for (int o = 16; o; o >>= 1) s += __shfl_xor_sync(0xffffffffu, s, o);
    if (lane == 0) red[warp] = s;
    __syncthreads();
    if (tid == 0) {
        float t = 0;
        #pragma unroll
        for (int w = 0; w < 8; w++) t += red[w];
        bc = t * (1.f / DMOD);
    }
    __syncthreads();
    float mu = bc;
    __syncthreads();

    float d0 = v0 - mu, d1 = v1 - mu;
    float q = d0 * d0 + d1 * d1;
    #pragma unroll
    for (int o = 16; o; o >>= 1) q += __shfl_xor_sync(0xffffffffu, q, o);
    if (lane == 0) red[warp] = q;
    __syncthreads();
    if (tid == 0) {
        float t = 0;
        #pragma unroll
        for (int w = 0; w < 8; w++) t += red[w];
        bc = t * (1.f / DMOD);
    }
    __syncthreads();
    float inv = rsqrtf(bc + 1e-5f);

    float* o = g_cw + (size_t)row * DMOD;
    o[tid]       = d0 * inv * gw[tid]       + gb[tid];
    o[tid + 256] = d1 * inv * gw[tid + 256] + gb[tid + 256];
}

// ---------------------------------------------------------------------------
// K7: mask + log_softmax over R=64 (one warp per row, in-place on d_out)
// ---------------------------------------------------------------------------
__global__ __launch_bounds__(256)
void lsm_kernel(float* __restrict__ out) {
    int warp = threadIdx.x >> 5, lane = threadIdx.x & 31;
    int row = blockIdx.x * 8 + warp;
    int b = row >> 12, i = (row >> 6) & 63, j = row & 63;
    float m = fminf(g_mask[b * ENT + i], 1.f) * fminf(g_mask[b * ENT + j], 1.f);
    float* p = out + (size_t)row * REL;
    float v0 = p[lane] * m, v1 = p[lane + 32] * m;
    float mx = fmaxf(v0, v1);
    #pragma unroll
    for (int o = 16; o; o >>= 1) mx = fmaxf(mx, __shfl_xor_sync(0xffffffffu, mx, o));
    float s = expf(v0 - mx) + expf(v1 - mx);
    #pragma unroll
    for (int o = 16; o; o >>= 1) s += __shfl_xor_sync(0xffffffffu, s, o);
    float lse = mx + logf(s);
    p[lane] = v0 - lse;
    p[lane + 32] = v1 - lse;
}

// ---------------------------------------------------------------------------
// Host launch
// ---------------------------------------------------------------------------
extern "C" void kernel_launch(void* const* d_in, const int* in_sizes, int n_in,
                              void* d_out, int out_size) {
    int off = (in_sizes[2] == 1) ? 0 : -1;
    const unsigned* sents_raw = (const unsigned*)d_in[0];
    const unsigned* ent_raw   = (const unsigned*)d_in[1];
    const float* emb    = (const float*)d_in[3 + off];
    const float* Wih    = (const float*)d_in[4 + off];
    const float* Whh    = (const float*)d_in[5 + off];
    const float* bih    = (const float*)d_in[6 + off];
    const float* bhh    = (const float*)d_in[7 + off];
    const float* ln_g   = (const float*)d_in[8 + off];
    const float* ln_b   = (const float*)d_in[9 + off];
    const float* rel1_w = (const float*)d_in[10 + off];
    const float* rel1_b = (const float*)d_in[11 + off];
    const float* rel2_w = (const float*)d_in[12 + off];
    const float* rel2_b = (const float*)d_in[13 + off];
    const float* proj_w = (const float*)d_in[14 + off];
    const float* proj_b = (const float*)d_in[15 + off];
    const float* dec_w  = (const float*)d_in[16 + off];
    const float* dec_b  = (const float*)d_in[17 + off];
    float* out = (float*)d_out;

    float *p_xw, *p_bias, *p_cw, *p_r1, *p_r2;
    __nv_bfloat16 *p_xb, *p_cwb, *p_Tb, *p_wihb, *p_r1b, *p_r2b, *p_pjb, *p_dcb;
    cudaGetSymbolAddress((void**)&p_xw, g_xw);
    cudaGetSymbolAddress((void**)&p_bias, g_bias);
    cudaGetSymbolAddress((void**)&p_cw, g_cw);
    cudaGetSymbolAddress((void**)&p_r1, g_rel1);
    cudaGetSymbolAddress((void**)&p_r2, g_rel2);
    cudaGetSymbolAddress((void**)&p_xb, g_xb);
    cudaGetSymbolAddress((void**)&p_cwb, g_cwb);
    cudaGetSymbolAddress((void**)&p_Tb, g_Tb);
    cudaGetSymbolAddress((void**)&p_wihb, g_wihb);
    cudaGetSymbolAddress((void**)&p_r1b, g_r1b);
    cudaGetSymbolAddress((void**)&p_r2b, g_r2b);
    cudaGetSymbolAddress((void**)&p_pjb, g_pjb);
    cudaGetSymbolAddress((void**)&p_dcb, g_dcb);

    prep_idx_kernel<<<1, 256>>>(sents_raw, ent_raw);
    prep_bias_kernel<<<16, 256>>>(bih, bhh);
    f2b_kernel<<<2048, 256>>>(Wih, p_wihb, NLAY * 2 * G4 * DMOD / 4);
    f2b_kernel<<<256, 256>>>(rel1_w, p_r1b, DMOD * DMOD / 4);
    f2b_kernel<<<256, 256>>>(rel2_w, p_r2b, DMOD * DMOD / 4);
    f2b_kernel<<<256, 256>>>(proj_w, p_pjb, DMOD * DMOD / 4);
    f2b_kernel<<<32, 256>>>(dec_w, p_dcb, REL * DMOD / 4);
    embed_kernel<<<MBT, 128>>>(emb);

    for (int l = 0; l < NLAY; l++) {
        for (int dir = 0; dir < 2; dir++) {
            hgemm_nt<false, false, false><<<dim3(G4 / 64, MBT / 128), 256>>>(
                p_xb, p_wihb + (size_t)(l * 2 + dir) * G4 * DMOD,
                p_bias + (l * 2 + dir) * G4,
                p_xw + (size_t)dir * MBT * G4, nullptr,
                MBT, G4, DMOD, nullptr, nullptr);
        }
        // writes bf16 y into g_xb (next layer's input / final pooling source)
        lstm_mma_kernel<<<64, 256>>>(
            p_xw, Whh + (size_t)l * 2 * G4 * HID, p_xb);
    }

    zero_kernel<<<1024, 256>>>();
    span_pool_kernel<<<MENT, 128>>>(p_xb);
    ln_kernel<<<MENT, 256>>>(ln_g, ln_b);
    f2b_kernel<<<(MENT * DMOD / 4 + 255) / 256, 256>>>(p_cw, p_cwb, MENT * DMOD / 4);

    hgemm_nt<false, false, false><<<dim3(DMOD / 64, MENT / 128), 256>>>(
        p_cwb, p_r1b, rel1_b, p_r1, nullptr, MENT, DMOD, DMOD, nullptr, nullptr);
    hgemm_nt<false, false, false><<<dim3(DMOD / 64, MENT / 128), 256>>>(
        p_cwb, p_r2b, rel2_b, p_r2, nullptr, MENT, DMOD, DMOD, nullptr, nullptr);

    // pairwise: Tb = relu( relu(r1_j + r2_i) @ proj_w.T + proj_b )  (bf16 out)
    hgemm_nt<true, true, true><<<dim3(DMOD / 64, MPAIR / 128), 256>>>(
        nullptr, p_pjb, proj_b, nullptr, p_Tb, MPAIR, DMOD, DMOD, p_r1, p_r2);

    // logits = Tb @ dec_w.T + dec_b  -> d_out (fp32)
    hgemm_nt<false, false, false><<<dim3(REL / 64, MPAIR / 128), 256>>>(
        p_Tb, p_dcb, dec_b, out, nullptr, MPAIR, REL, DMOD, nullptr, nullptr);

    lsm_kernel<<<MPAIR / 8, 256>>>(out);
}

// round 16
// speedup vs baseline: 1.3926x; 1.3926x over previous
#include <cuda_runtime.h>
#include <cuda_bf16.h>
#include <cstddef>

// ---------------------------------------------------------------------------
// Problem constants
// ---------------------------------------------------------------------------
#define BATCH 32
#define SEQT  512
#define DMOD  512
#define HID   256
#define G4    1024          // 4*HID
#define ENT   64
#define REL   64
#define NLAY  2
#define MBT   (BATCH*SEQT)          // 16384 token rows
#define MPAIR (BATCH*ENT*ENT)       // 131072 pair rows
#define MENT  (BATCH*ENT)           // 2048 entity rows

// ---------------------------------------------------------------------------
// Device scratch (static allocation only — no cudaMalloc allowed)
// ---------------------------------------------------------------------------
__device__ __nv_bfloat16  g_xb[(size_t)MBT * DMOD];        // bf16 activations
__device__ float          g_xw[(size_t)2 * MBT * G4];      // per-dir input proj (fp32)
__device__ float          g_bias[NLAY * 2 * G4];           // bih+bhh
__device__ int            g_sents[MBT];
__device__ int            g_ent[MENT * 3];
__device__ float          g_cont[(size_t)MENT * DMOD];
__device__ float          g_mask[MENT];
__device__ float          g_cw[(size_t)MENT * DMOD];
__device__ __nv_bfloat16  g_cwb[(size_t)MENT * DMOD];
__device__ float          g_rel1[(size_t)MENT * DMOD];
__device__ float          g_rel2[(size_t)MENT * DMOD];
__device__ __nv_bfloat16  g_Tb[(size_t)MPAIR * DMOD];      // pair hidden, bf16
// bf16 weight copies
__device__ __nv_bfloat16  g_wihb[(size_t)NLAY * 2 * G4 * DMOD];
__device__ __nv_bfloat16  g_r1b[DMOD * DMOD];
__device__ __nv_bfloat16  g_r2b[DMOD * DMOD];
__device__ __nv_bfloat16  g_pjb[DMOD * DMOD];
__device__ __nv_bfloat16  g_dcb[REL * DMOD];

__device__ __forceinline__ float tanh_a(float x) {
    float r;
    asm("tanh.approx.f32 %0, %1;" : "=f"(r) : "f"(x));
    return r;
}
__device__ __forceinline__ float sigm_a(float x) {
    return fmaf(tanh_a(0.5f * x), 0.5f, 0.5f);
}

// ---------------------------------------------------------------------------
// K0: canonicalize sents / ent_inds (int64-or-int32 auto-detect) -> int32
// ---------------------------------------------------------------------------
__global__ void prep_idx_kernel(const unsigned* __restrict__ sents_raw,
                                const unsigned* __restrict__ ent_raw) {
    __shared__ int s64f, e64f;
    int tid = threadIdx.x;
    if (tid == 0) {
        bool s64 = true;
        for (int i = 0; i < 64; i++)
            if (sents_raw[2 * i + 1] != 0u) { s64 = false; break; }
        bool e64 = true;
        for (int i = 0; i < 64; i++) {
            unsigned lo = ent_raw[2 * i], hi = ent_raw[2 * i + 1];
            unsigned expct = ((int)lo < 0) ? 0xFFFFFFFFu : 0u;
            if (hi != expct) { e64 = false; break; }
        }
        s64f = s64; e64f = e64;
    }
    __syncthreads();
    int s64 = s64f, e64 = e64f;
    for (int i = tid; i < MBT; i += blockDim.x)
        g_sents[i] = s64 ? (int)sents_raw[2 * i] : (int)sents_raw[i];
    for (int i = tid; i < MENT * 3; i += blockDim.x)
        g_ent[i] = e64 ? (int)ent_raw[2 * i] : (int)ent_raw[i];
}

__global__ void prep_bias_kernel(const float* __restrict__ bih,
                                 const float* __restrict__ bhh) {
    int i = blockIdx.x * blockDim.x + threadIdx.x;
    if (i < NLAY * 2 * G4) g_bias[i] = bih[i] + bhh[i];
}

// ---------------------------------------------------------------------------
// f32 -> bf16 vectorized convert (n4 float4-groups)
// ---------------------------------------------------------------------------
__global__ void f2b_kernel(const float* __restrict__ src,
                           __nv_bfloat16* __restrict__ dst, int n4) {
    int i = blockIdx.x * blockDim.x + threadIdx.x;
    if (i >= n4) return;
    float4 v = reinterpret_cast<const float4*>(src)[i];
    __nv_bfloat162 lo = __float22bfloat162_rn(make_float2(v.x, v.y));
    __nv_bfloat162 hi = __float22bfloat162_rn(make_float2(v.z, v.w));
    uint2 u;
    u.x = *reinterpret_cast<unsigned*>(&lo);
    u.y = *reinterpret_cast<unsigned*>(&hi);
    reinterpret_cast<uint2*>(dst)[i] = u;
}

// ---------------------------------------------------------------------------
// K2: embedding gather -> bf16 activations
// ---------------------------------------------------------------------------
__global__ void embed_kernel(const float* __restrict__ emb) {
    int row = blockIdx.x;
    int d = threadIdx.x;                               // 128 float4 lanes
    int tok = g_sents[row];
    float4 v = reinterpret_cast<const float4*>(emb + (size_t)tok * DMOD)[d];
    __nv_bfloat162 lo = __float22bfloat162_rn(make_float2(v.x, v.y));
    __nv_bfloat162 hi = __float22bfloat162_rn(make_float2(v.z, v.w));
    uint2 u;
    u.x = *reinterpret_cast<unsigned*>(&lo);
    u.y = *reinterpret_cast<unsigned*>(&hi);
    reinterpret_cast<uint2*>(g_xb + (size_t)row * DMOD)[d] = u;
}

// ---------------------------------------------------------------------------
// bf16 tensor-core GEMM: C[M,N] = A[M,K] @ W[N,K]^T + bias, fp32 accum.
// BM=128 BN=64 BK=32, 256 thr (8 warps, 4x2), warp tile 32x32 via mma.m16n8k16.
// Double-buffered smem + ldmatrix.x4 fragment loads. Non-GEN path stages via
// cp.async (GMEM->SMEM direct, overlapped with mma); GEN path computes A in
// registers and stores manually (R14 structure).
// ---------------------------------------------------------------------------
template <bool GEN, bool OUTB, bool RELU>
__global__ __launch_bounds__(256)
void hgemm_nt(const __nv_bfloat16* __restrict__ A,
              const __nv_bfloat16* __restrict__ Bw,
              const float* __restrict__ bias,
              float* __restrict__ Cf, __nv_bfloat16* __restrict__ Cb,
              int M, int N, int K,
              const float* __restrict__ r1, const float* __restrict__ r2) {
    const int BM = 128, BN = 64, BK = 32, LDA = BK + 8;   // 80-byte rows (16B mult)
    __shared__ __align__(16) __nv_bfloat16 As[2][BM * LDA];
    __shared__ __align__(16) __nv_bfloat16 Bs[2][BN * LDA];
    int tid = threadIdx.x;
    int row0 = blockIdx.y * BM, col0 = blockIdx.x * BN;

    int ar[2], ac[2];
    #pragma unroll
    for (int q = 0; q < 2; q++) {
        int idx = tid + q * 256;
        ar[q] = idx >> 2;
        ac[q] = (idx & 3) * 8;
    }
    int br = tid >> 2, bc = (tid & 3) * 8;

    float acc[2][4][4];
    #pragma unroll
    for (int i = 0; i < 2; i++)
        #pragma unroll
        for (int j = 0; j < 4; j++)
            #pragma unroll
            for (int c = 0; c < 4; c++) acc[i][j][c] = 0.f;

    unsigned sAraw = (unsigned)__cvta_generic_to_shared(&As[0][0]);
    unsigned sBraw = (unsigned)__cvta_generic_to_shared(&Bs[0][0]);
    const unsigned bufAB = (unsigned)(BM * LDA * 2);
    const unsigned bufBB = (unsigned)(BN * LDA * 2);

    // async staging of one k-tile into buffer `buf` (non-GEN path)
    auto copyTile = [&](int kt, int buf) {
        #pragma unroll
        for (int q = 0; q < 2; q++) {
            unsigned d = sAraw + buf * bufAB + (unsigned)((ar[q] * LDA + ac[q]) * 2);
            const void* s = A + (size_t)(row0 + ar[q]) * K + kt + ac[q];
            asm volatile("cp.async.ca.shared.global [%0], [%1], 16;"
                         :: "r"(d), "l"(s) : "memory");
        }
        unsigned d = sBraw + buf * bufBB + (unsigned)((br * LDA + bc) * 2);
        const void* s = Bw + (size_t)(col0 + br) * K + kt + bc;
        asm volatile("cp.async.ca.shared.global [%0], [%1], 16;"
                     :: "r"(d), "l"(s) : "memory");
        asm volatile("cp.async.commit_group;" ::: "memory");
    };

    // manual fetch/stage (GEN path: A generated on the fly, B via LDG)
    uint4 ua[2], ub;
    auto fetch = [&](int kt) {
        #pragma unroll
        for (int q = 0; q < 2; q++) {
            int m = row0 + ar[q];
            int bb = m >> 12, ii = (m >> 6) & 63, jj = m & 63;
            const float4* p1 = reinterpret_cast<const float4*>(
                r1 + ((size_t)(bb * ENT + jj)) * DMOD + kt + ac[q]);
            const float4* p2 = reinterpret_cast<const float4*>(
                r2 + ((size_t)(bb * ENT + ii)) * DMOD + kt + ac[q]);
            float4 x0 = p1[0], x1 = p1[1], y0 = p2[0], y1 = p2[1];
            float f0 = fmaxf(x0.x + y0.x, 0.f), f1 = fmaxf(x0.y + y0.y, 0.f);
            float f2 = fmaxf(x0.z + y0.z, 0.f), f3 = fmaxf(x0.w + y0.w, 0.f);
            float f4 = fmaxf(x1.x + y1.x, 0.f), f5 = fmaxf(x1.y + y1.y, 0.f);
            float f6 = fmaxf(x1.z + y1.z, 0.f), f7 = fmaxf(x1.w + y1.w, 0.f);
            __nv_bfloat162 h0 = __float22bfloat162_rn(make_float2(f0, f1));
            __nv_bfloat162 h1 = __float22bfloat162_rn(make_float2(f2, f3));
            __nv_bfloat162 h2 = __float22bfloat162_rn(make_float2(f4, f5));
            __nv_bfloat162 h3 = __float22bfloat162_rn(make_float2(f6, f7));
            ua[q].x = *reinterpret_cast<unsigned*>(&h0);
            ua[q].y = *reinterpret_cast<unsigned*>(&h1);
            ua[q].z = *reinterpret_cast<unsigned*>(&h2);
            ua[q].w = *reinterpret_cast<unsigned*>(&h3);
        }
        ub = *reinterpret_cast<const uint4*>(Bw + (size_t)(col0 + br) * K + kt + bc);
    };
    auto stage = [&](int buf) {
        *reinterpret_cast<uint4*>(&As[buf][ar[0] * LDA + ac[0]]) = ua[0];
        *reinterpret_cast<uint4*>(&As[buf][ar[1] * LDA + ac[1]]) = ua[1];
        *reinterpret_cast<uint4*>(&Bs[buf][br * LDA + bc]) = ub;
    };

    int w = tid >> 5, wm = w & 3, wn = w >> 2, l = tid & 31;
    int lr = l >> 2, lc = (l & 3) * 2;

    int a_row = wm * 32 + ((l >> 3) & 1) * 8 + (l & 7);
    int a_col = (l >> 4) * 8;
    int b_row = wn * 32 + (l >> 4) * 8 + (l & 7);
    int b_col = ((l >> 3) & 1) * 8;
    unsigned aAddr = sAraw + (unsigned)((a_row * LDA + a_col) * 2);
    unsigned bAddr = sBraw + (unsigned)((b_row * LDA + b_col) * 2);

    if (GEN) {
        fetch(0);
        stage(0);
    } else {
        copyTile(0, 0);
        asm volatile("cp.async.wait_group 0;" ::: "memory");
    }
    __syncthreads();

    int nk = K / BK;
    for (int kt = 0; kt < nk; kt++) {
        int cur = kt & 1;
        if (kt + 1 < nk) {
            if (GEN) fetch((kt + 1) * BK);
            else     copyTile((kt + 1) * BK, cur ^ 1);
        }

        unsigned aBuf = aAddr + cur * bufAB;
        unsigned bBuf = bAddr + cur * bufBB;
        #pragma unroll
        for (int s = 0; s < 2; s++) {
            unsigned a[2][4], b[4][2];
            #pragma unroll
            for (int i = 0; i < 2; i++) {
                unsigned ad = aBuf + (unsigned)((i * 16 * LDA + s * 16) * 2);
                asm volatile(
                    "ldmatrix.sync.aligned.m8n8.x4.shared.b16 {%0,%1,%2,%3}, [%4];"
                    : "=r"(a[i][0]), "=r"(a[i][1]), "=r"(a[i][2]), "=r"(a[i][3])
                    : "r"(ad));
            }
            #pragma unroll
            for (int jp = 0; jp < 2; jp++) {
                unsigned bd = bBuf + (unsigned)((jp * 16 * LDA + s * 16) * 2);
                asm volatile(
                    "ldmatrix.sync.aligned.m8n8.x4.shared.b16 {%0,%1,%2,%3}, [%4];"
                    : "=r"(b[2 * jp][0]), "=r"(b[2 * jp][1]),
                      "=r"(b[2 * jp + 1][0]), "=r"(b[2 * jp + 1][1])
                    : "r"(bd));
            }
            #pragma unroll
            for (int i = 0; i < 2; i++)
                #pragma unroll
                for (int j = 0; j < 4; j++)
                    asm volatile(
                        "mma.sync.aligned.m16n8k16.row.col.f32.bf16.bf16.f32 "
                        "{%0,%1,%2,%3},{%4,%5,%6,%7},{%8,%9},{%0,%1,%2,%3};"
                        : "+f"(acc[i][j][0]), "+f"(acc[i][j][1]),
                          "+f"(acc[i][j][2]), "+f"(acc[i][j][3])
                        : "r"(a[i][0]), "r"(a[i][1]), "r"(a[i][2]), "r"(a[i][3]),
                          "r"(b[j][0]), "r"(b[j][1]));
        }

        if (kt + 1 < nk) {
            if (GEN) {
                stage(cur ^ 1);
            } else {
                asm volatile("cp.async.wait_group 0;" ::: "memory");
            }
            __syncthreads();
        }
    }

    // epilogue
    #pragma unroll
    for (int i = 0; i < 2; i++) {
        int m = row0 + wm * 32 + i * 16 + lr;
        #pragma unroll
        for (int j = 0; j < 4; j++) {
            int col = col0 + wn * 32 + j * 8 + lc;
            float b0 = bias[col], b1 = bias[col + 1];
            float v0 = acc[i][j][0] + b0, v1 = acc[i][j][1] + b1;
            float v2 = acc[i][j][2] + b0, v3 = acc[i][j][3] + b1;
            if (RELU) {
                v0 = fmaxf(v0, 0.f); v1 = fmaxf(v1, 0.f);
                v2 = fmaxf(v2, 0.f); v3 = fmaxf(v3, 0.f);
            }
            if (OUTB) {
                __nv_bfloat162 p0 = __float22bfloat162_rn(make_float2(v0, v1));
                __nv_bfloat162 p1 = __float22bfloat162_rn(make_float2(v2, v3));
                *reinterpret_cast<__nv_bfloat162*>(Cb + (size_t)m * N + col) = p0;
                *reinterpret_cast<__nv_bfloat162*>(Cb + (size_t)(m + 8) * N + col) = p1;
            } else {
                *reinterpret_cast<float2*>(Cf + (size_t)m * N + col) = make_float2(v0, v1);
                *reinterpret_cast<float2*>(Cf + (size_t)(m + 8) * N + col) = make_float2(v2, v3);
            }
        }
    }
}

// ---------------------------------------------------------------------------
// K3: LSTM recurrence on tensor cores, 4-CTA cluster, 2 batches per cluster.
// R13/R14 winner (unchanged): fp32 x-proj, per-step hardware cluster.sync,
// 128 B-fragment registers/thread, 128 owner threads (one activation chain
// each), hoisted cluster arrive, bf16-only y.
// ---------------------------------------------------------------------------
__global__ void __cluster_dims__(4, 1, 1) __launch_bounds__(256, 1)
lstm_mma_kernel(const float* __restrict__ xw,
                const float* __restrict__ whh_l,   // fp32 [2][G4][HID]
                __nv_bfloat16* __restrict__ yb) {
    __shared__ __align__(16) __nv_bfloat16 hA[2][2][264];  // [par][batch][k]
    __shared__ __align__(16) float zs[2][260];             // [batch][n]

    int tid = threadIdx.x;
    int w = tid >> 5, l = tid & 31;
    int gq = l >> 2, t2 = (l & 3) * 2;
    int rank = blockIdx.x & 3;
    int cid  = blockIdx.x >> 2;
    int dir  = cid >> 4;
    int bp   = cid & 15;
    int j0   = rank * 64;

    // zero h staging (both parities)
    for (int i = tid; i < 2 * 2 * 264; i += 256)
        (&hA[0][0][0])[i] = __float2bfloat16(0.f);

    // ---- B-fragment preload: W[n][k] resident in registers ----------------
    unsigned Bf[4][16][2];
    {
        const float* wd = whh_l + (size_t)dir * G4 * HID;
        #pragma unroll
        for (int nt = 0; nt < 4; nt++) {
            int n = w * 32 + nt * 8 + gq;            // CTA-local gate index
            int g = n >> 6, jl = n & 63;
            const float* wp = wd + (size_t)(g * 256 + j0 + jl) * HID;
            #pragma unroll
            for (int kt = 0; kt < 16; kt++) {
                int k0 = kt * 16 + t2;
                float2 wa = *reinterpret_cast<const float2*>(wp + k0);
                float2 wb = *reinterpret_cast<const float2*>(wp + k0 + 8);
                __nv_bfloat162 qa = __float22bfloat162_rn(wa);
                __nv_bfloat162 qb = __float22bfloat162_rn(wb);
                Bf[nt][kt][0] = *reinterpret_cast<unsigned*>(&qa);
                Bf[nt][kt][1] = *reinterpret_cast<unsigned*>(&qb);
            }
        }
    }
    __syncthreads();
    asm volatile("barrier.cluster.arrive.aligned;" ::: "memory");
    asm volatile("barrier.cluster.wait.aligned;" ::: "memory");

    int bg0 = bp * 2;
    const float* xd = xw + (size_t)dir * MBT * G4;
    int xcol = (w >> 1) * 256 + j0 + (w & 1) * 32;   // global z-col base
    int brow = gq & 1;                               // A-row (= batch) for lanes 0-7

    // owner mapping: tid<128 -> batch ob, j-local ojl
    int ob = tid >> 6, ojl = tid & 63;
    int ojg = j0 + ojl;
    size_t yoff = ((size_t)(bg0 + ob) * SEQT) * DMOD + dir * HID + ojg;
    float cst = 0.f;

    unsigned hAbase;
    asm("{ .reg .u64 t; cvta.to.shared.u64 t, %1; cvt.u32.u64 %0, t; }"
        : "=r"(hAbase) : "l"(&hA[0][0][0]));

    // first step's x (accumulator init values, lanes 0-7)
    float2 xi[4];
    {
        int t0 = dir ? SEQT - 1 : 0;
        #pragma unroll
        for (int nt = 0; nt < 4; nt++) {
            xi[nt] = make_float2(0.f, 0.f);
            if (l < 8)
                xi[nt] = *reinterpret_cast<const float2*>(
                    xd + ((size_t)(bg0 + brow) * SEQT + t0) * G4 + xcol + nt * 8 + t2);
        }
    }

    unsigned zc = 0u;
    int par = 0;
    for (int s = 0; s < SEQT; s++) {
        int t = dir ? (SEQT - 1 - s) : s;

        // prefetch next step's x
        int sn = (s + 1 < SEQT) ? s + 1 : s;
        int tn = dir ? (SEQT - 1 - sn) : sn;
        float2 xn[4];
        #pragma unroll
        for (int nt = 0; nt < 4; nt++) {
            xn[nt] = make_float2(0.f, 0.f);
            if (l < 8)
                xn[nt] = *reinterpret_cast<const float2*>(
                    xd + ((size_t)(bg0 + brow) * SEQT + tn) * G4 + xcol + nt * 8 + t2);
        }

        // accumulators = x (bias folded); rows 8,9 unused -> 0
        float acc[4][4];
        #pragma unroll
        for (int nt = 0; nt < 4; nt++) {
            acc[nt][0] = xi[nt].x; acc[nt][1] = xi[nt].y;
            acc[nt][2] = 0.f;      acc[nt][3] = 0.f;
        }

        // mma over k = 256 (16 tiles)
        const __nv_bfloat16* hrow = &hA[par][brow][0];
        #pragma unroll
        for (int kt = 0; kt < 16; kt++) {
            unsigned a0 = 0u, a2 = 0u;
            if (l < 8) {
                a0 = *reinterpret_cast<const unsigned*>(hrow + kt * 16 + t2);
                a2 = *reinterpret_cast<const unsigned*>(hrow + kt * 16 + t2 + 8);
            }
            #pragma unroll
            for (int nt = 0; nt < 4; nt++)
                asm volatile(
                    "mma.sync.aligned.m16n8k16.row.col.f32.bf16.bf16.f32 "
                    "{%0,%1,%2,%3},{%4,%5,%6,%7},{%8,%9},{%0,%1,%2,%3};"
                    : "+f"(acc[nt][0]), "+f"(acc[nt][1]),
                      "+f"(acc[nt][2]), "+f"(acc[nt][3])
                    : "r"(a0), "r"(zc), "r"(a2), "r"(zc),
                      "r"(Bf[nt][kt][0]), "r"(Bf[nt][kt][1]));
        }

        // z -> smem (lanes 0-7 hold rows 0,1)
        if (l < 8) {
            #pragma unroll
            for (int nt = 0; nt < 4; nt++)
                *reinterpret_cast<float2*>(&zs[brow][w * 32 + nt * 8 + t2]) =
                    make_float2(acc[nt][0], acc[nt][1]);
        }
        __syncthreads();

        // owners (tid<128): one activation chain each + DSMEM broadcast
        __nv_bfloat16 hbq = __float2bfloat16(0.f);
        if (tid < 128) {
            float z0 = zs[ob][0 * 64 + ojl];
            float z1 = zs[ob][1 * 64 + ojl];
            float z2 = zs[ob][2 * 64 + ojl];
            float z3 = zs[ob][3 * 64 + ojl];
            cst = sigm_a(z1) * cst + sigm_a(z0) * tanh_a(z2);
            float h = sigm_a(z3) * tanh_a(cst);
            hbq = __float2bfloat16(h);

            unsigned uv = (unsigned)__bfloat16_as_ushort(hbq);
            unsigned nv = __shfl_down_sync(0xffffffffu, uv, 1);
            if (!(ojl & 1)) {
                unsigned pk = uv | (nv << 16);
                unsigned dst = hAbase +
                    (unsigned)((((par ^ 1) * 2 + ob) * 264 + ojg) * 2);
                #pragma unroll
                for (int r = 0; r < 4; r++) {
                    asm volatile(
                        "{ .reg .b32 ra; mapa.shared::cluster.u32 ra, %0, %1; "
                        "st.shared::cluster.b32 [ra], %2; }"
                        :: "r"(dst), "r"(r), "r"(pk) : "memory");
                }
            }
        }
        // arrive first; y store retires inside the barrier window
        asm volatile("barrier.cluster.arrive.aligned;" ::: "memory");
        if (tid < 128)
            yb[yoff + (size_t)t * DMOD] = hbq;
        asm volatile("barrier.cluster.wait.aligned;" ::: "memory");

        par ^= 1;
        #pragma unroll
        for (int nt = 0; nt < 4; nt++) xi[nt] = xn[nt];
    }
}

// ---------------------------------------------------------------------------
// K4: zero cont + mask
// ---------------------------------------------------------------------------
__global__ void zero_kernel() {
    int idx = blockIdx.x * blockDim.x + threadIdx.x;
    const int NC4 = (MENT * DMOD) / 4;
    if (idx < NC4) reinterpret_cast<float4*>(g_cont)[idx] = make_float4(0, 0, 0, 0);
    if (idx < MENT / 4) reinterpret_cast<float4*>(g_mask)[idx] = make_float4(0, 0, 0, 0);
}

// ---------------------------------------------------------------------------
// K5: ragged span mean-pool + scatter-add (atomic); reads bf16 activations
// ---------------------------------------------------------------------------
__global__ void span_pool_kernel(const __nv_bfloat16* __restrict__ x) {
    int be = blockIdx.x;
    int b = be >> 6;
    const int* ei = g_ent + be * 3;
    int id = ei[0], st = ei[1], en = ei[2];
    if (id < 0 || id >= ENT) return;
    int lo = st, hi = en;
    float sgn = 1.f;
    if (en < st) { lo = en; hi = st; sgn = -1.f; }
    lo = max(lo, 0); hi = min(hi, SEQT);
    float len = (float)max(en - st, 1);

    int d = threadIdx.x;                 // 128 lanes, 4 bf16 each
    float4 acc = make_float4(0, 0, 0, 0);
    const uint2* xp =
        reinterpret_cast<const uint2*>(x + (size_t)b * SEQT * DMOD) + d;
    for (int t = lo; t < hi; t++) {
        uint2 u = xp[(size_t)t * (DMOD / 4)];
        float2 a = __bfloat1622float2(*reinterpret_cast<__nv_bfloat162*>(&u.x));
        float2 bb = __bfloat1622float2(*reinterpret_cast<__nv_bfloat162*>(&u.y));
        acc.x += a.x; acc.y += a.y; acc.z += bb.x; acc.w += bb.y;
    }
    float invl = sgn / len;
    float* cp = g_cont + ((size_t)(b * ENT + id)) * DMOD + d * 4;
    atomicAdd(cp + 0, acc.x * invl);
    atomicAdd(cp + 1, acc.y * invl);
    atomicAdd(cp + 2, acc.z * invl);
    atomicAdd(cp + 3, acc.w * invl);
    if (d == 0) atomicAdd(&g_mask[b * ENT + id], 1.f);
}

// ---------------------------------------------------------------------------
// K6: LayerNorm over D=512 -> fp32 cw
// ---------------------------------------------------------------------------
__global__ __launch_bounds__(256)
void ln_kernel(const float* __restrict__ gw, const float* __restrict__ gb) {
    int row = blockIdx.x;
    int tid = threadIdx.x;
    const float* xr = g_cont + (size_t)row * DMOD;
    float v0 = xr[tid], v1 = xr[tid + 256];

    __shared__ float red[8];
    __shared__ float bc;
    int lane = tid & 31, warp = tid >> 5;

    float s = v0 + v1;
    #pragma unroll
    for (int o = 16; o; o >>= 1) s += __shfl_xor_sync(0xffffffffu, s, o);
    if (lane == 0) red[warp] = s;
    __syncthreads();
    if (tid == 0) {
        float t = 0;
        #pragma unroll
        for (int w = 0; w < 8; w++) t += red[w];
        bc = t * (1.f / DMOD);
    }
    __syncthreads();
    float mu = bc;
    __syncthreads();

    float d0 = v0 - mu, d1 = v1 - mu;
    float q = d0 * d0 + d1 * d1;
    #pragma unroll
    for (int o = 16; o; o >>= 1) q += __shfl_xor_sync(0xffffffffu, q, o);
    if (lane == 0) red[warp] = q;
    __syncthreads();
    if (tid == 0) {
        float t = 0;
        #pragma unroll
        for (int w = 0; w < 8; w++) t += red[w];
        bc = t * (1.f / DMOD);
    }
    __syncthreads();
    float inv = rsqrtf(bc + 1e-5f);

    float* o = g_cw + (size_t)row * DMOD;
    o[tid]       = d0 * inv * gw[tid]       + gb[tid];
    o[tid + 256] = d1 * inv * gw[tid + 256] + gb[tid + 256];
}

// ---------------------------------------------------------------------------
// K7: mask + log_softmax over R=64 (one warp per row, in-place on d_out)
// ---------------------------------------------------------------------------
__global__ __launch_bounds__(256)
void lsm_kernel(float* __restrict__ out) {
    int warp = threadIdx.x >> 5, lane = threadIdx.x & 31;
    int row = blockIdx.x * 8 + warp;
    int b = row >> 12, i = (row >> 6) & 63, j = row & 63;
    float m = fminf(g_mask[b * ENT + i], 1.f) * fminf(g_mask[b * ENT + j], 1.f);
    float* p = out + (size_t)row * REL;
    float v0 = p[lane] * m, v1 = p[lane + 32] * m;
    float mx = fmaxf(v0, v1);
    #pragma unroll
    for (int o = 16; o; o >>= 1) mx = fmaxf(mx, __shfl_xor_sync(0xffffffffu, mx, o));
    float s = expf(v0 - mx) + expf(v1 - mx);
    #pragma unroll
    for (int o = 16; o; o >>= 1) s += __shfl_xor_sync(0xffffffffu, s, o);
    float lse = mx + logf(s);
    p[lane] = v0 - lse;
    p[lane + 32] = v1 - lse;
}

// ---------------------------------------------------------------------------
// Host launch
// ---------------------------------------------------------------------------
extern "C" void kernel_launch(void* const* d_in, const int* in_sizes, int n_in,
                              void* d_out, int out_size) {
    int off = (in_sizes[2] == 1) ? 0 : -1;
    const unsigned* sents_raw = (const unsigned*)d_in[0];
    const unsigned* ent_raw   = (const unsigned*)d_in[1];
    const float* emb    = (const float*)d_in[3 + off];
    const float* Wih    = (const float*)d_in[4 + off];
    const float* Whh    = (const float*)d_in[5 + off];
    const float* bih    = (const float*)d_in[6 + off];
    const float* bhh    = (const float*)d_in[7 + off];
    const float* ln_g   = (const float*)d_in[8 + off];
    const float* ln_b   = (const float*)d_in[9 + off];
    const float* rel1_w = (const float*)d_in[10 + off];
    const float* rel1_b = (const float*)d_in[11 + off];
    const float* rel2_w = (const float*)d_in[12 + off];
    const float* rel2_b = (const float*)d_in[13 + off];
    const float* proj_w = (const float*)d_in[14 + off];
    const float* proj_b = (const float*)d_in[15 + off];
    const float* dec_w  = (const float*)d_in[16 + off];
    const float* dec_b  = (const float*)d_in[17 + off];
    float* out = (float*)d_out;

    float *p_xw, *p_bias, *p_cw, *p_r1, *p_r2;
    __nv_bfloat16 *p_xb, *p_cwb, *p_Tb, *p_wihb, *p_r1b, *p_r2b, *p_pjb, *p_dcb;
    cudaGetSymbolAddress((void**)&p_xw, g_xw);
    cudaGetSymbolAddress((void**)&p_bias, g_bias);
    cudaGetSymbolAddress((void**)&p_cw, g_cw);
    cudaGetSymbolAddress((void**)&p_r1, g_rel1);
    cudaGetSymbolAddress((void**)&p_r2, g_rel2);
    cudaGetSymbolAddress((void**)&p_xb, g_xb);
    cudaGetSymbolAddress((void**)&p_cwb, g_cwb);
    cudaGetSymbolAddress((void**)&p_Tb, g_Tb);
    cudaGetSymbolAddress((void**)&p_wihb, g_wihb);
    cudaGetSymbolAddress((void**)&p_r1b, g_r1b);
    cudaGetSymbolAddress((void**)&p_r2b, g_r2b);
    cudaGetSymbolAddress((void**)&p_pjb, g_pjb);
    cudaGetSymbolAddress((void**)&p_dcb, g_dcb);

    prep_idx_kernel<<<1, 256>>>(sents_raw, ent_raw);
    prep_bias_kernel<<<16, 256>>>(bih, bhh);
    f2b_kernel<<<2048, 256>>>(Wih, p_wihb, NLAY * 2 * G4 * DMOD / 4);
    f2b_kernel<<<256, 256>>>(rel1_w, p_r1b, DMOD * DMOD / 4);
    f2b_kernel<<<256, 256>>>(rel2_w, p_r2b, DMOD * DMOD / 4);
    f2b_kernel<<<256, 256>>>(proj_w, p_pjb, DMOD * DMOD / 4);
    f2b_kernel<<<32, 256>>>(dec_w, p_dcb, REL * DMOD / 4);
    embed_kernel<<<MBT, 128>>>(emb);

    for (int l = 0; l < NLAY; l++) {
        for (int dir = 0; dir < 2; dir++) {
            hgemm_nt<false, false, false><<<dim3(G4 / 64, MBT / 128), 256>>>(
                p_xb, p_wihb + (size_t)(l * 2 + dir) * G4 * DMOD,
                p_bias + (l * 2 + dir) * G4,
                p_xw + (size_t)dir * MBT * G4, nullptr,
                MBT, G4, DMOD, nullptr, nullptr);
        }
        // writes bf16 y into g_xb (next layer's input / final pooling source)
        lstm_mma_kernel<<<128, 256>>>(
            p_xw, Whh + (size_t)l * 2 * G4 * HID, p_xb);
    }

    zero_kernel<<<1024, 256>>>();
    span_pool_kernel<<<MENT, 128>>>(p_xb);
    ln_kernel<<<MENT, 256>>>(ln_g, ln_b);
    f2b_kernel<<<(MENT * DMOD / 4 + 255) / 256, 256>>>(p_cw, p_cwb, MENT * DMOD / 4);

    hgemm_nt<false, false, false><<<dim3(DMOD / 64, MENT / 128), 256>>>(
        p_cwb, p_r1b, rel1_b, p_r1, nullptr, MENT, DMOD, DMOD, nullptr, nullptr);
    hgemm_nt<false, false, false><<<dim3(DMOD / 64, MENT / 128), 256>>>(
        p_cwb, p_r2b, rel2_b, p_r2, nullptr, MENT, DMOD, DMOD, nullptr, nullptr);

    // pairwise: Tb = relu( relu(r1_j + r2_i) @ proj_w.T + proj_b )  (bf16 out)
    hgemm_nt<true, true, true><<<dim3(DMOD / 64, MPAIR / 128), 256>>>(
        nullptr, p_pjb, proj_b, nullptr, p_Tb, MPAIR, DMOD, DMOD, p_r1, p_r2);

    // logits = Tb @ dec_w.T + dec_b  -> d_out (fp32)
    hgemm_nt<false, false, false><<<dim3(REL / 64, MPAIR / 128), 256>>>(
        p_Tb, p_dcb, dec_b, out, nullptr, MPAIR, REL, DMOD, nullptr, nullptr);

    lsm_kernel<<<MPAIR / 8, 256>>>(out);
}

// round 17
// speedup vs baseline: 1.4616x; 1.0496x over previous
#include <cuda_runtime.h>
#include <cuda_bf16.h>
#include <cstddef>

// ---------------------------------------------------------------------------
// Problem constants
// ---------------------------------------------------------------------------
#define BATCH 32
#define SEQT  512
#define DMOD  512
#define HID   256
#define G4    1024          // 4*HID
#define ENT   64
#define REL   64
#define NLAY  2
#define MBT   (BATCH*SEQT)          // 16384 token rows
#define MPAIR (BATCH*ENT*ENT)       // 131072 pair rows
#define MENT  (BATCH*ENT)           // 2048 entity rows

// ---------------------------------------------------------------------------
// Device scratch (static allocation only — no cudaMalloc allowed)
// ---------------------------------------------------------------------------
__device__ __nv_bfloat16  g_xb[(size_t)MBT * DMOD];        // bf16 activations
__device__ float          g_xw[(size_t)2 * MBT * G4];      // per-dir input proj (fp32)
__device__ float          g_bias[NLAY * 2 * G4];           // bih+bhh
__device__ int            g_sents[MBT];
__device__ int            g_ent[MENT * 3];
__device__ float          g_cont[(size_t)MENT * DMOD];
__device__ float          g_mask[MENT];
__device__ float          g_cw[(size_t)MENT * DMOD];
__device__ __nv_bfloat16  g_cwb[(size_t)MENT * DMOD];
__device__ __nv_bfloat16  g_e1b[(size_t)MENT * DMOD];      // rel1 output (bf16)
__device__ __nv_bfloat16  g_e2b[(size_t)MENT * DMOD];      // rel2 output (bf16)
__device__ __nv_bfloat16  g_Tb[(size_t)MPAIR * DMOD];      // pair hidden, bf16
// bf16 weight copies
__device__ __nv_bfloat16  g_wihb[(size_t)NLAY * 2 * G4 * DMOD];
__device__ __nv_bfloat16  g_r1b[DMOD * DMOD];
__device__ __nv_bfloat16  g_r2b[DMOD * DMOD];
__device__ __nv_bfloat16  g_pjb[DMOD * DMOD];
__device__ __nv_bfloat16  g_dcb[REL * DMOD];

__device__ __forceinline__ float tanh_a(float x) {
    float r;
    asm("tanh.approx.f32 %0, %1;" : "=f"(r) : "f"(x));
    return r;
}
__device__ __forceinline__ float sigm_a(float x) {
    return fmaf(tanh_a(0.5f * x), 0.5f, 0.5f);
}

// ---------------------------------------------------------------------------
// K0: canonicalize sents / ent_inds (int64-or-int32 auto-detect) -> int32
// ---------------------------------------------------------------------------
__global__ void prep_idx_kernel(const unsigned* __restrict__ sents_raw,
                                const unsigned* __restrict__ ent_raw) {
    __shared__ int s64f, e64f;
    int tid = threadIdx.x;
    if (tid == 0) {
        bool s64 = true;
        for (int i = 0; i < 64; i++)
            if (sents_raw[2 * i + 1] != 0u) { s64 = false; break; }
        bool e64 = true;
        for (int i = 0; i < 64; i++) {
            unsigned lo = ent_raw[2 * i], hi = ent_raw[2 * i + 1];
            unsigned expct = ((int)lo < 0) ? 0xFFFFFFFFu : 0u;
            if (hi != expct) { e64 = false; break; }
        }
        s64f = s64; e64f = e64;
    }
    __syncthreads();
    int s64 = s64f, e64 = e64f;
    for (int i = tid; i < MBT; i += blockDim.x)
        g_sents[i] = s64 ? (int)sents_raw[2 * i] : (int)sents_raw[i];
    for (int i = tid; i < MENT * 3; i += blockDim.x)
        g_ent[i] = e64 ? (int)ent_raw[2 * i] : (int)ent_raw[i];
}

__global__ void prep_bias_kernel(const float* __restrict__ bih,
                                 const float* __restrict__ bhh) {
    int i = blockIdx.x * blockDim.x + threadIdx.x;
    if (i < NLAY * 2 * G4) g_bias[i] = bih[i] + bhh[i];
}

// ---------------------------------------------------------------------------
// f32 -> bf16 vectorized convert (n4 float4-groups)
// ---------------------------------------------------------------------------
__global__ void f2b_kernel(const float* __restrict__ src,
                           __nv_bfloat16* __restrict__ dst, int n4) {
    int i = blockIdx.x * blockDim.x + threadIdx.x;
    if (i >= n4) return;
    float4 v = reinterpret_cast<const float4*>(src)[i];
    __nv_bfloat162 lo = __float22bfloat162_rn(make_float2(v.x, v.y));
    __nv_bfloat162 hi = __float22bfloat162_rn(make_float2(v.z, v.w));
    uint2 u;
    u.x = *reinterpret_cast<unsigned*>(&lo);
    u.y = *reinterpret_cast<unsigned*>(&hi);
    reinterpret_cast<uint2*>(dst)[i] = u;
}

// ---------------------------------------------------------------------------
// K2: embedding gather -> bf16 activations
// ---------------------------------------------------------------------------
__global__ void embed_kernel(const float* __restrict__ emb) {
    int row = blockIdx.x;
    int d = threadIdx.x;                               // 128 float4 lanes
    int tok = g_sents[row];
    float4 v = reinterpret_cast<const float4*>(emb + (size_t)tok * DMOD)[d];
    __nv_bfloat162 lo = __float22bfloat162_rn(make_float2(v.x, v.y));
    __nv_bfloat162 hi = __float22bfloat162_rn(make_float2(v.z, v.w));
    uint2 u;
    u.x = *reinterpret_cast<unsigned*>(&lo);
    u.y = *reinterpret_cast<unsigned*>(&hi);
    reinterpret_cast<uint2*>(g_xb + (size_t)row * DMOD)[d] = u;
}

// ---------------------------------------------------------------------------
// bf16 tensor-core GEMM: C[M,N] = A[M,K] @ W[N,K]^T + bias, fp32 accum.
// BM=128 BN=64 BK=32, 256 thr (8 warps, 4x2), warp tile 32x32 via mma.m16n8k16.
// Double-buffered smem + ldmatrix.x4. Non-GEN stages via cp.async.
// GEN: A = relu(r1b[b,j] + r2b[b,i]) computed in packed bf16 (hadd2/hmax2).
// LSM: N==REL epilogue computes masked log_softmax per row into Cf.
// ---------------------------------------------------------------------------
template <bool GEN, bool OUTB, bool RELU, bool LSM>
__global__ __launch_bounds__(256)
void hgemm_nt(const __nv_bfloat16* __restrict__ A,
              const __nv_bfloat16* __restrict__ Bw,
              const float* __restrict__ bias,
              float* __restrict__ Cf, __nv_bfloat16* __restrict__ Cb,
              int M, int N, int K,
              const __nv_bfloat16* __restrict__ r1,
              const __nv_bfloat16* __restrict__ r2) {
    const int BM = 128, BN = 64, BK = 32, LDA = BK + 8;   // 80-byte rows (16B mult)
    __shared__ __align__(16) __nv_bfloat16 As[2][BM * LDA];
    __shared__ __align__(16) __nv_bfloat16 Bs[2][BN * LDA];
    __shared__ float rred[2][BM];      // LSM cross-warp row reduction
    int tid = threadIdx.x;
    int row0 = blockIdx.y * BM, col0 = blockIdx.x * BN;

    int ar[2], ac[2];
    #pragma unroll
    for (int q = 0; q < 2; q++) {
        int idx = tid + q * 256;
        ar[q] = idx >> 2;
        ac[q] = (idx & 3) * 8;
    }
    int br = tid >> 2, bc = (tid & 3) * 8;

    float acc[2][4][4];
    #pragma unroll
    for (int i = 0; i < 2; i++)
        #pragma unroll
        for (int j = 0; j < 4; j++)
            #pragma unroll
            for (int c = 0; c < 4; c++) acc[i][j][c] = 0.f;

    unsigned sAraw = (unsigned)__cvta_generic_to_shared(&As[0][0]);
    unsigned sBraw = (unsigned)__cvta_generic_to_shared(&Bs[0][0]);
    const unsigned bufAB = (unsigned)(BM * LDA * 2);
    const unsigned bufBB = (unsigned)(BN * LDA * 2);

    // async staging of one k-tile into buffer `buf` (non-GEN path)
    auto copyTile = [&](int kt, int buf) {
        #pragma unroll
        for (int q = 0; q < 2; q++) {
            unsigned d = sAraw + buf * bufAB + (unsigned)((ar[q] * LDA + ac[q]) * 2);
            const void* s = A + (size_t)(row0 + ar[q]) * K + kt + ac[q];
            asm volatile("cp.async.ca.shared.global [%0], [%1], 16;"
                         :: "r"(d), "l"(s) : "memory");
        }
        unsigned d = sBraw + buf * bufBB + (unsigned)((br * LDA + bc) * 2);
        const void* s = Bw + (size_t)(col0 + br) * K + kt + bc;
        asm volatile("cp.async.ca.shared.global [%0], [%1], 16;"
                     :: "r"(d), "l"(s) : "memory");
        asm volatile("cp.async.commit_group;" ::: "memory");
    };

    // manual fetch/stage (GEN path: A generated on the fly in bf16, B via LDG)
    uint4 ua[2], ub;
    auto fetch = [&](int kt) {
        __nv_bfloat162 z2 = __float2bfloat162_rn(0.f);
        #pragma unroll
        for (int q = 0; q < 2; q++) {
            int m = row0 + ar[q];
            int bb = m >> 12, ii = (m >> 6) & 63, jj = m & 63;
            uint4 u1 = *reinterpret_cast<const uint4*>(
                r1 + ((size_t)(bb * ENT + jj)) * DMOD + kt + ac[q]);
            uint4 u2 = *reinterpret_cast<const uint4*>(
                r2 + ((size_t)(bb * ENT + ii)) * DMOD + kt + ac[q]);
            auto f = [&](unsigned a, unsigned b) {
                __nv_bfloat162 s = __hadd2(*reinterpret_cast<__nv_bfloat162*>(&a),
                                           *reinterpret_cast<__nv_bfloat162*>(&b));
                s = __hmax2(s, z2);
                return *reinterpret_cast<unsigned*>(&s);
            };
            ua[q].x = f(u1.x, u2.x);
            ua[q].y = f(u1.y, u2.y);
            ua[q].z = f(u1.z, u2.z);
            ua[q].w = f(u1.w, u2.w);
        }
        ub = *reinterpret_cast<const uint4*>(Bw + (size_t)(col0 + br) * K + kt + bc);
    };
    auto stage = [&](int buf) {
        *reinterpret_cast<uint4*>(&As[buf][ar[0] * LDA + ac[0]]) = ua[0];
        *reinterpret_cast<uint4*>(&As[buf][ar[1] * LDA + ac[1]]) = ua[1];
        *reinterpret_cast<uint4*>(&Bs[buf][br * LDA + bc]) = ub;
    };

    int w = tid >> 5, wm = w & 3, wn = w >> 2, l = tid & 31;
    int lr = l >> 2, lc = (l & 3) * 2;

    int a_row = wm * 32 + ((l >> 3) & 1) * 8 + (l & 7);
    int a_col = (l >> 4) * 8;
    int b_row = wn * 32 + (l >> 4) * 8 + (l & 7);
    int b_col = ((l >> 3) & 1) * 8;
    unsigned aAddr = sAraw + (unsigned)((a_row * LDA + a_col) * 2);
    unsigned bAddr = sBraw + (unsigned)((b_row * LDA + b_col) * 2);

    if (GEN) {
        fetch(0);
        stage(0);
    } else {
        copyTile(0, 0);
        asm volatile("cp.async.wait_group 0;" ::: "memory");
    }
    __syncthreads();

    int nk = K / BK;
    for (int kt = 0; kt < nk; kt++) {
        int cur = kt & 1;
        if (kt + 1 < nk) {
            if (GEN) fetch((kt + 1) * BK);
            else     copyTile((kt + 1) * BK, cur ^ 1);
        }

        unsigned aBuf = aAddr + cur * bufAB;
        unsigned bBuf = bAddr + cur * bufBB;
        #pragma unroll
        for (int s = 0; s < 2; s++) {
            unsigned a[2][4], b[4][2];
            #pragma unroll
            for (int i = 0; i < 2; i++) {
                unsigned ad = aBuf + (unsigned)((i * 16 * LDA + s * 16) * 2);
                asm volatile(
                    "ldmatrix.sync.aligned.m8n8.x4.shared.b16 {%0,%1,%2,%3}, [%4];"
                    : "=r"(a[i][0]), "=r"(a[i][1]), "=r"(a[i][2]), "=r"(a[i][3])
                    : "r"(ad));
            }
            #pragma unroll
            for (int jp = 0; jp < 2; jp++) {
                unsigned bd = bBuf + (unsigned)((jp * 16 * LDA + s * 16) * 2);
                asm volatile(
                    "ldmatrix.sync.aligned.m8n8.x4.shared.b16 {%0,%1,%2,%3}, [%4];"
                    : "=r"(b[2 * jp][0]), "=r"(b[2 * jp][1]),
                      "=r"(b[2 * jp + 1][0]), "=r"(b[2 * jp + 1][1])
                    : "r"(bd));
            }
            #pragma unroll
            for (int i = 0; i < 2; i++)
                #pragma unroll
                for (int j = 0; j < 4; j++)
                    asm volatile(
                        "mma.sync.aligned.m16n8k16.row.col.f32.bf16.bf16.f32 "
                        "{%0,%1,%2,%3},{%4,%5,%6,%7},{%8,%9},{%0,%1,%2,%3};"
                        : "+f"(acc[i][j][0]), "+f"(acc[i][j][1]),
                          "+f"(acc[i][j][2]), "+f"(acc[i][j][3])
                        : "r"(a[i][0]), "r"(a[i][1]), "r"(a[i][2]), "r"(a[i][3]),
                          "r"(b[j][0]), "r"(b[j][1]));
        }

        if (kt + 1 < nk) {
            if (GEN) {
                stage(cur ^ 1);
            } else {
                asm volatile("cp.async.wait_group 0;" ::: "memory");
            }
            __syncthreads();
        }
    }

    if (LSM) {
        // masked log_softmax over the row (N == 64, whole row in this CTA).
        // Each thread holds 4 rows x 8 vals: row r -> wm*32 + (r>>1)*16 + (r&1)*8 + lr
        float v[4][8], gm[4];
        #pragma unroll
        for (int i = 0; i < 2; i++) {
            #pragma unroll
            for (int half = 0; half < 2; half++) {
                int m = row0 + wm * 32 + i * 16 + half * 8 + lr;
                int b = m >> 12, ei = (m >> 6) & 63, ej = m & 63;
                float mk = fminf(g_mask[b * ENT + ei], 1.f) *
                           fminf(g_mask[b * ENT + ej], 1.f);
                #pragma unroll
                for (int j = 0; j < 4; j++) {
                    int col = wn * 32 + j * 8 + lc;
                    v[i * 2 + half][j * 2 + 0] = (acc[i][j][half * 2 + 0] + bias[col]) * mk;
                    v[i * 2 + half][j * 2 + 1] = (acc[i][j][half * 2 + 1] + bias[col + 1]) * mk;
                }
            }
        }
        __syncthreads();     // As/Bs no longer needed; protect rred reuse
        #pragma unroll
        for (int r = 0; r < 4; r++) {
            float mx = v[r][0];
            #pragma unroll
            for (int q = 1; q < 8; q++) mx = fmaxf(mx, v[r][q]);
            mx = fmaxf(mx, __shfl_xor_sync(0xffffffffu, mx, 1));
            mx = fmaxf(mx, __shfl_xor_sync(0xffffffffu, mx, 2));
            if ((l & 3) == 0)
                rred[wn][wm * 32 + (r >> 1) * 16 + (r & 1) * 8 + lr] = mx;
            gm[r] = mx;
        }
        __syncthreads();
        #pragma unroll
        for (int r = 0; r < 4; r++) {
            int lrow = wm * 32 + (r >> 1) * 16 + (r & 1) * 8 + lr;
            gm[r] = fmaxf(rred[0][lrow], rred[1][lrow]);
        }
        __syncthreads();
        float sm[4];
        #pragma unroll
        for (int r = 0; r < 4; r++) {
            float s = 0.f;
            #pragma unroll
            for (int q = 0; q < 8; q++) s += expf(v[r][q] - gm[r]);
            s += __shfl_xor_sync(0xffffffffu, s, 1);
            s += __shfl_xor_sync(0xffffffffu, s, 2);
            if ((l & 3) == 0)
                rred[wn][wm * 32 + (r >> 1) * 16 + (r & 1) * 8 + lr] = s;
            sm[r] = s;
        }
        __syncthreads();
        #pragma unroll
        for (int r = 0; r < 4; r++) {
            int lrow = wm * 32 + (r >> 1) * 16 + (r & 1) * 8 + lr;
            float lse = gm[r] + logf(rred[0][lrow] + rred[1][lrow]);
            int m = row0 + lrow;
            #pragma unroll
            for (int j = 0; j < 4; j++) {
                int col = wn * 32 + j * 8 + lc;
                *reinterpret_cast<float2*>(Cf + (size_t)m * N + col) =
                    make_float2(v[r][j * 2] - lse, v[r][j * 2 + 1] - lse);
            }
        }
        return;
    }

    // standard epilogue
    #pragma unroll
    for (int i = 0; i < 2; i++) {
        int m = row0 + wm * 32 + i * 16 + lr;
        #pragma unroll
        for (int j = 0; j < 4; j++) {
            int col = col0 + wn * 32 + j * 8 + lc;
            float b0 = bias[col], b1 = bias[col + 1];
            float v0 = acc[i][j][0] + b0, v1 = acc[i][j][1] + b1;
            float v2 = acc[i][j][2] + b0, v3 = acc[i][j][3] + b1;
            if (RELU) {
                v0 = fmaxf(v0, 0.f); v1 = fmaxf(v1, 0.f);
                v2 = fmaxf(v2, 0.f); v3 = fmaxf(v3, 0.f);
            }
            if (OUTB) {
                __nv_bfloat162 p0 = __float22bfloat162_rn(make_float2(v0, v1));
                __nv_bfloat162 p1 = __float22bfloat162_rn(make_float2(v2, v3));
                *reinterpret_cast<__nv_bfloat162*>(Cb + (size_t)m * N + col) = p0;
                *reinterpret_cast<__nv_bfloat162*>(Cb + (size_t)(m + 8) * N + col) = p1;
            } else {
                *reinterpret_cast<float2*>(Cf + (size_t)m * N + col) = make_float2(v0, v1);
                *reinterpret_cast<float2*>(Cf + (size_t)(m + 8) * N + col) = make_float2(v2, v3);
            }
        }
    }
}

// ---------------------------------------------------------------------------
// K3: LSTM recurrence on tensor cores, 4-CTA cluster, 2 batches per cluster.
// R13/R14/R16 winner (unchanged).
// ---------------------------------------------------------------------------
__global__ void __cluster_dims__(4, 1, 1) __launch_bounds__(256, 1)
lstm_mma_kernel(const float* __restrict__ xw,
                const float* __restrict__ whh_l,   // fp32 [2][G4][HID]
                __nv_bfloat16* __restrict__ yb) {
    __shared__ __align__(16) __nv_bfloat16 hA[2][2][264];  // [par][batch][k]
    __shared__ __align__(16) float zs[2][260];             // [batch][n]

    int tid = threadIdx.x;
    int w = tid >> 5, l = tid & 31;
    int gq = l >> 2, t2 = (l & 3) * 2;
    int rank = blockIdx.x & 3;
    int cid  = blockIdx.x >> 2;
    int dir  = cid >> 4;
    int bp   = cid & 15;
    int j0   = rank * 64;

    // zero h staging (both parities)
    for (int i = tid; i < 2 * 2 * 264; i += 256)
        (&hA[0][0][0])[i] = __float2bfloat16(0.f);

    // ---- B-fragment preload: W[n][k] resident in registers ----------------
    unsigned Bf[4][16][2];
    {
        const float* wd = whh_l + (size_t)dir * G4 * HID;
        #pragma unroll
        for (int nt = 0; nt < 4; nt++) {
            int n = w * 32 + nt * 8 + gq;            // CTA-local gate index
            int g = n >> 6, jl = n & 63;
            const float* wp = wd + (size_t)(g * 256 + j0 + jl) * HID;
            #pragma unroll
            for (int kt = 0; kt < 16; kt++) {
                int k0 = kt * 16 + t2;
                float2 wa = *reinterpret_cast<const float2*>(wp + k0);
                float2 wb = *reinterpret_cast<const float2*>(wp + k0 + 8);
                __nv_bfloat162 qa = __float22bfloat162_rn(wa);
                __nv_bfloat162 qb = __float22bfloat162_rn(wb);
                Bf[nt][kt][0] = *reinterpret_cast<unsigned*>(&qa);
                Bf[nt][kt][1] = *reinterpret_cast<unsigned*>(&qb);
            }
        }
    }
    __syncthreads();
    asm volatile("barrier.cluster.arrive.aligned;" ::: "memory");
    asm volatile("barrier.cluster.wait.aligned;" ::: "memory");

    int bg0 = bp * 2;
    const float* xd = xw + (size_t)dir * MBT * G4;
    int xcol = (w >> 1) * 256 + j0 + (w & 1) * 32;   // global z-col base
    int brow = gq & 1;                               // A-row (= batch) for lanes 0-7

    // owner mapping: tid<128 -> batch ob, j-local ojl
    int ob = tid >> 6, ojl = tid & 63;
    int ojg = j0 + ojl;
    size_t yoff = ((size_t)(bg0 + ob) * SEQT) * DMOD + dir * HID + ojg;
    float cst = 0.f;

    unsigned hAbase;
    asm("{ .reg .u64 t; cvta.to.shared.u64 t, %1; cvt.u32.u64 %0, t; }"
        : "=r"(hAbase) : "l"(&hA[0][0][0]));

    // first step's x (accumulator init values, lanes 0-7)
    float2 xi[4];
    {
        int t0 = dir ? SEQT - 1 : 0;
        #pragma unroll
        for (int nt = 0; nt < 4; nt++) {
            xi[nt] = make_float2(0.f, 0.f);
            if (l < 8)
                xi[nt] = *reinterpret_cast<const float2*>(
                    xd + ((size_t)(bg0 + brow) * SEQT + t0) * G4 + xcol + nt * 8 + t2);
        }
    }

    unsigned zc = 0u;
    int par = 0;
    for (int s = 0; s < SEQT; s++) {
        int t = dir ? (SEQT - 1 - s) : s;

        // prefetch next step's x
        int sn = (s + 1 < SEQT) ? s + 1 : s;
        int tn = dir ? (SEQT - 1 - sn) : sn;
        float2 xn[4];
        #pragma unroll
        for (int nt = 0; nt < 4; nt++) {
            xn[nt] = make_float2(0.f, 0.f);
            if (l < 8)
                xn[nt] = *reinterpret_cast<const float2*>(
                    xd + ((size_t)(bg0 + brow) * SEQT + tn) * G4 + xcol + nt * 8 + t2);
        }

        // accumulators = x (bias folded); rows 8,9 unused -> 0
        float acc[4][4];
        #pragma unroll
        for (int nt = 0; nt < 4; nt++) {
            acc[nt][0] = xi[nt].x; acc[nt][1] = xi[nt].y;
            acc[nt][2] = 0.f;      acc[nt][3] = 0.f;
        }

        // mma over k = 256 (16 tiles)
        const __nv_bfloat16* hrow = &hA[par][brow][0];
        #pragma unroll
        for (int kt = 0; kt < 16; kt++) {
            unsigned a0 = 0u, a2 = 0u;
            if (l < 8) {
                a0 = *reinterpret_cast<const unsigned*>(hrow + kt * 16 + t2);
                a2 = *reinterpret_cast<const unsigned*>(hrow + kt * 16 + t2 + 8);
            }
            #pragma unroll
            for (int nt = 0; nt < 4; nt++)
                asm volatile(
                    "mma.sync.aligned.m16n8k16.row.col.f32.bf16.bf16.f32 "
                    "{%0,%1,%2,%3},{%4,%5,%6,%7},{%8,%9},{%0,%1,%2,%3};"
                    : "+f"(acc[nt][0]), "+f"(acc[nt][1]),
                      "+f"(acc[nt][2]), "+f"(acc[nt][3])
                    : "r"(a0), "r"(zc), "r"(a2), "r"(zc),
                      "r"(Bf[nt][kt][0]), "r"(Bf[nt][kt][1]));
        }

        // z -> smem (lanes 0-7 hold rows 0,1)
        if (l < 8) {
            #pragma unroll
            for (int nt = 0; nt < 4; nt++)
                *reinterpret_cast<float2*>(&zs[brow][w * 32 + nt * 8 + t2]) =
                    make_float2(acc[nt][0], acc[nt][1]);
        }
        __syncthreads();

        // owners (tid<128): one activation chain each + DSMEM broadcast
        __nv_bfloat16 hbq = __float2bfloat16(0.f);
        if (tid < 128) {
            float z0 = zs[ob][0 * 64 + ojl];
            float z1 = zs[ob][1 * 64 + ojl];
            float z2 = zs[ob][2 * 64 + ojl];
            float z3 = zs[ob][3 * 64 + ojl];
            cst = sigm_a(z1) * cst + sigm_a(z0) * tanh_a(z2);
            float h = sigm_a(z3) * tanh_a(cst);
            hbq = __float2bfloat16(h);

            unsigned uv = (unsigned)__bfloat16_as_ushort(hbq);
            unsigned nv = __shfl_down_sync(0xffffffffu, uv, 1);
            if (!(ojl & 1)) {
                unsigned pk = uv | (nv << 16);
                unsigned dst = hAbase +
                    (unsigned)((((par ^ 1) * 2 + ob) * 264 + ojg) * 2);
                #pragma unroll
                for (int r = 0; r < 4; r++) {
                    asm volatile(
                        "{ .reg .b32 ra; mapa.shared::cluster.u32 ra, %0, %1; "
                        "st.shared::cluster.b32 [ra], %2; }"
                        :: "r"(dst), "r"(r), "r"(pk) : "memory");
                }
            }
        }
        // arrive first; y store retires inside the barrier window
        asm volatile("barrier.cluster.arrive.aligned;" ::: "memory");
        if (tid < 128)
            yb[yoff + (size_t)t * DMOD] = hbq;
        asm volatile("barrier.cluster.wait.aligned;" ::: "memory");

        par ^= 1;
        #pragma unroll
        for (int nt = 0; nt < 4; nt++) xi[nt] = xn[nt];
    }
}

// ---------------------------------------------------------------------------
// K4: zero cont + mask
// ---------------------------------------------------------------------------
__global__ void zero_kernel() {
    int idx = blockIdx.x * blockDim.x + threadIdx.x;
    const int NC4 = (MENT * DMOD) / 4;
    if (idx < NC4) reinterpret_cast<float4*>(g_cont)[idx] = make_float4(0, 0, 0, 0);
    if (idx < MENT / 4) reinterpret_cast<float4*>(g_mask)[idx] = make_float4(0, 0, 0, 0);
}

// ---------------------------------------------------------------------------
// K5: ragged span mean-pool + scatter-add (atomic); reads bf16 activations
// ---------------------------------------------------------------------------
__global__ void span_pool_kernel(const __nv_bfloat16* __restrict__ x) {
    int be = blockIdx.x;
    int b = be >> 6;
    const int* ei = g_ent + be * 3;
    int id = ei[0], st = ei[1], en = ei[2];
    if (id < 0 || id >= ENT) return;
    int lo = st, hi = en;
    float sgn = 1.f;
    if (en < st) { lo = en; hi = st; sgn = -1.f; }
    lo = max(lo, 0); hi = min(hi, SEQT);
    float len = (float)max(en - st, 1);

    int d = threadIdx.x;                 // 128 lanes, 4 bf16 each
    float4 acc = make_float4(0, 0, 0, 0);
    const uint2* xp =
        reinterpret_cast<const uint2*>(x + (size_t)b * SEQT * DMOD) + d;
    for (int t = lo; t < hi; t++) {
        uint2 u = xp[(size_t)t * (DMOD / 4)];
        float2 a = __bfloat1622float2(*reinterpret_cast<__nv_bfloat162*>(&u.x));
        float2 bb = __bfloat1622float2(*reinterpret_cast<__nv_bfloat162*>(&u.y));
        acc.x += a.x; acc.y += a.y; acc.z += bb.x; acc.w += bb.y;
    }
    float invl = sgn / len;
    float* cp = g_cont + ((size_t)(b * ENT + id)) * DMOD + d * 4;
    atomicAdd(cp + 0, acc.x * invl);
    atomicAdd(cp + 1, acc.y * invl);
    atomicAdd(cp + 2, acc.z * invl);
    atomicAdd(cp + 3, acc.w * invl);
    if (d == 0) atomicAdd(&g_mask[b * ENT + id], 1.f);
}

// ---------------------------------------------------------------------------
// K6: LayerNorm over D=512 -> fp32 cw
// ---------------------------------------------------------------------------
__global__ __launch_bounds__(256)
void ln_kernel(const float* __restrict__ gw, const float* __restrict__ gb) {
    int row = blockIdx.x;
    int tid = threadIdx.x;
    const float* xr = g_cont + (size_t)row * DMOD;
    float v0 = xr[tid], v1 = xr[tid + 256];

    __shared__ float red[8];
    __shared__ float bc;
    int lane = tid & 31, warp = tid >> 5;

    float s = v0 + v1;
    #pragma unroll
    for (int o = 16; o; o >>= 1) s += __shfl_xor_sync(0xffffffffu, s, o);
    if (lane == 0) red[warp] = s;
    __syncthreads();
    if (tid == 0) {
        float t = 0;
        #pragma unroll
        for (int w = 0; w < 8; w++) t += red[w];
        bc = t * (1.f / DMOD);
    }
    __syncthreads();
    float mu = bc;
    __syncthreads();

    float d0 = v0 - mu, d1 = v1 - mu;
    float q = d0 * d0 + d1 * d1;
    #pragma unroll
    for (int o = 16; o; o >>= 1) q += __shfl_xor_sync(0xffffffffu, q, o);
    if (lane == 0) red[warp] = q;
    __syncthreads();
    if (tid == 0) {
        float t = 0;
        #pragma unroll
        for (int w = 0; w < 8; w++) t += red[w];
        bc = t * (1.f / DMOD);
    }
    __syncthreads();
    float inv = rsqrtf(bc + 1e-5f);

    float* o = g_cw + (size_t)row * DMOD;
    o[tid]       = d0 * inv * gw[tid]       + gb[tid];
    o[tid + 256] = d1 * inv * gw[tid + 256] + gb[tid + 256];
}

// ---------------------------------------------------------------------------
// Host launch
// ---------------------------------------------------------------------------
extern "C" void kernel_launch(void* const* d_in, const int* in_sizes, int n_in,
                              void* d_out, int out_size) {
    int off = (in_sizes[2] == 1) ? 0 : -1;
    const unsigned* sents_raw = (const unsigned*)d_in[0];
    const unsigned* ent_raw   = (const unsigned*)d_in[1];
    const float* emb    = (const float*)d_in[3 + off];
    const float* Wih    = (const float*)d_in[4 + off];
    const float* Whh    = (const float*)d_in[5 + off];
    const float* bih    = (const float*)d_in[6 + off];
    const float* bhh    = (const float*)d_in[7 + off];
    const float* ln_g   = (const float*)d_in[8 + off];
    const float* ln_b   = (const float*)d_in[9 + off];
    const float* rel1_w = (const float*)d_in[10 + off];
    const float* rel1_b = (const float*)d_in[11 + off];
    const float* rel2_w = (const float*)d_in[12 + off];
    const float* rel2_b = (const float*)d_in[13 + off];
    const float* proj_w = (const float*)d_in[14 + off];
    const float* proj_b = (const float*)d_in[15 + off];
    const float* dec_w  = (const float*)d_in[16 + off];
    const float* dec_b  = (const float*)d_in[17 + off];
    float* out = (float*)d_out;

    float *p_xw, *p_bias, *p_cw;
    __nv_bfloat16 *p_xb, *p_cwb, *p_Tb, *p_wihb, *p_r1b, *p_r2b, *p_pjb, *p_dcb;
    __nv_bfloat16 *p_e1b, *p_e2b;
    cudaGetSymbolAddress((void**)&p_xw, g_xw);
    cudaGetSymbolAddress((void**)&p_bias, g_bias);
    cudaGetSymbolAddress((void**)&p_cw, g_cw);
    cudaGetSymbolAddress((void**)&p_xb, g_xb);
    cudaGetSymbolAddress((void**)&p_cwb, g_cwb);
    cudaGetSymbolAddress((void**)&p_Tb, g_Tb);
    cudaGetSymbolAddress((void**)&p_wihb, g_wihb);
    cudaGetSymbolAddress((void**)&p_r1b, g_r1b);
    cudaGetSymbolAddress((void**)&p_r2b, g_r2b);
    cudaGetSymbolAddress((void**)&p_pjb, g_pjb);
    cudaGetSymbolAddress((void**)&p_dcb, g_dcb);
    cudaGetSymbolAddress((void**)&p_e1b, g_e1b);
    cudaGetSymbolAddress((void**)&p_e2b, g_e2b);

    prep_idx_kernel<<<1, 256>>>(sents_raw, ent_raw);
    prep_bias_kernel<<<16, 256>>>(bih, bhh);
    f2b_kernel<<<2048, 256>>>(Wih, p_wihb, NLAY * 2 * G4 * DMOD / 4);
    f2b_kernel<<<256, 256>>>(rel1_w, p_r1b, DMOD * DMOD / 4);
    f2b_kernel<<<256, 256>>>(rel2_w, p_r2b, DMOD * DMOD / 4);
    f2b_kernel<<<256, 256>>>(proj_w, p_pjb, DMOD * DMOD / 4);
    f2b_kernel<<<32, 256>>>(dec_w, p_dcb, REL * DMOD / 4);
    embed_kernel<<<MBT, 128>>>(emb);

    for (int l = 0; l < NLAY; l++) {
        for (int dir = 0; dir < 2; dir++) {
            hgemm_nt<false, false, false, false><<<dim3(G4 / 64, MBT / 128), 256>>>(
                p_xb, p_wihb + (size_t)(l * 2 + dir) * G4 * DMOD,
                p_bias + (l * 2 + dir) * G4,
                p_xw + (size_t)dir * MBT * G4, nullptr,
                MBT, G4, DMOD, nullptr, nullptr);
        }
        // writes bf16 y into g_xb (next layer's input / final pooling source)
        lstm_mma_kernel<<<128, 256>>>(
            p_xw, Whh + (size_t)l * 2 * G4 * HID, p_xb);
    }

    zero_kernel<<<1024, 256>>>();
    span_pool_kernel<<<MENT, 128>>>(p_xb);
    ln_kernel<<<MENT, 256>>>(ln_g, ln_b);
    f2b_kernel<<<(MENT * DMOD / 4 + 255) / 256, 256>>>(p_cw, p_cwb, MENT * DMOD / 4);

    // rel1/rel2 -> bf16 outputs (feed pairwise GEN path)
    hgemm_nt<false, true, false, false><<<dim3(DMOD / 64, MENT / 128), 256>>>(
        p_cwb, p_r1b, rel1_b, nullptr, p_e1b, MENT, DMOD, DMOD, nullptr, nullptr);
    hgemm_nt<false, true, false, false><<<dim3(DMOD / 64, MENT / 128), 256>>>(
        p_cwb, p_r2b, rel2_b, nullptr, p_e2b, MENT, DMOD, DMOD, nullptr, nullptr);

    // pairwise: Tb = relu( relu(r1_j + r2_i) @ proj_w.T + proj_b )  (bf16 out)
    hgemm_nt<true, true, true, false><<<dim3(DMOD / 64, MPAIR / 128), 256>>>(
        nullptr, p_pjb, proj_b, nullptr, p_Tb, MPAIR, DMOD, DMOD, p_e1b, p_e2b);

    // logits = Tb @ dec_w.T + dec_b, fused mask + log_softmax -> d_out
    hgemm_nt<false, false, false, true><<<dim3(REL / 64, MPAIR / 128), 256>>>(
        p_Tb, p_dcb, dec_b, out, nullptr, MPAIR, REL, DMOD, nullptr, nullptr);
}